// round 6
// baseline (speedup 1.0000x reference)
#include <cuda_runtime.h>
#include <cuda_bf16.h>
#include <math.h>
#include <stdint.h>

#define D_MODEL 1024
#define N_HEADS 16
#define HD 64
#define BATCH 2
#define SEQ 2048
#define M_TOTAL (BATCH * SEQ)   // 4096
#define QKV_N (3 * D_MODEL)     // 3072
#define KDIM 1024

// ---------------- scratch (device globals; allocation-free) ----------------
__device__ float g_qkv[(size_t)M_TOTAL * QKV_N];
__device__ float g_y[(size_t)M_TOTAL * D_MODEL];

__device__ __align__(256) __nv_bfloat16 g_x_hi[(size_t)M_TOTAL * KDIM];
__device__ __align__(256) __nv_bfloat16 g_x_lo[(size_t)M_TOTAL * KDIM];
__device__ __align__(256) __nv_bfloat16 g_y_hi[(size_t)M_TOTAL * KDIM];
__device__ __align__(256) __nv_bfloat16 g_y_lo[(size_t)M_TOTAL * KDIM];
__device__ __align__(256) __nv_bfloat16 g_wat_hi[(size_t)QKV_N * KDIM];   // W_attn^T [3072,1024]
__device__ __align__(256) __nv_bfloat16 g_wat_lo[(size_t)QKV_N * KDIM];
__device__ __align__(256) __nv_bfloat16 g_wpt_hi[(size_t)D_MODEL * KDIM]; // W_proj^T [1024,1024]
__device__ __align__(256) __nv_bfloat16 g_wpt_lo[(size_t)D_MODEL * KDIM];

// ---------------- helpers ----------------
__device__ __forceinline__ uint32_t smem_u32(const void* p) {
    uint32_t a;
    asm("{ .reg .u64 t; cvta.to.shared.u64 t, %1; cvt.u32.u64 %0, t; }"
        : "=r"(a) : "l"(p));
    return a;
}

__device__ __forceinline__ void cp16(uint32_t dst, const void* src) {
    asm volatile("cp.async.cg.shared.global [%0], [%1], 16;" :: "r"(dst), "l"(src));
}
#define CP_COMMIT() asm volatile("cp.async.commit_group;" ::: "memory")
#define CP_WAIT(n)  asm volatile("cp.async.wait_group %0;" :: "n"(n) : "memory")

__device__ __forceinline__ void ldsm_x4(uint32_t* r, uint32_t addr) {
    asm volatile("ldmatrix.sync.aligned.m8n8.x4.shared.b16 {%0,%1,%2,%3}, [%4];"
        : "=r"(r[0]), "=r"(r[1]), "=r"(r[2]), "=r"(r[3]) : "r"(addr));
}

__device__ __forceinline__ void mma_bf16(float* d, const uint32_t* a,
                                         uint32_t b0, uint32_t b1) {
    asm volatile(
        "mma.sync.aligned.m16n8k16.row.col.f32.bf16.bf16.f32 "
        "{%0,%1,%2,%3}, {%4,%5,%6,%7}, {%8,%9}, {%0,%1,%2,%3};"
        : "+f"(d[0]), "+f"(d[1]), "+f"(d[2]), "+f"(d[3])
        : "r"(a[0]), "r"(a[1]), "r"(a[2]), "r"(a[3]), "r"(b0), "r"(b1));
}

// ---------------- conversion kernels ----------------
__device__ __forceinline__ void split1(float v, __nv_bfloat16& h, __nv_bfloat16& l) {
    h = __float2bfloat16(v);
    l = __float2bfloat16(v - __bfloat162float(h));
}

__global__ void split_kernel(const float* __restrict__ in,
                             __nv_bfloat16* __restrict__ hi,
                             __nv_bfloat16* __restrict__ lo, int n)
{
    int idx = (blockIdx.x * blockDim.x + threadIdx.x) * 4;
    if (idx >= n) return;
    float4 v = *reinterpret_cast<const float4*>(in + idx);
    __nv_bfloat16 h0, h1, h2, h3, l0, l1, l2, l3;
    split1(v.x, h0, l0); split1(v.y, h1, l1);
    split1(v.z, h2, l2); split1(v.w, h3, l3);
    *reinterpret_cast<__nv_bfloat162*>(hi + idx)     = __nv_bfloat162(h0, h1);
    *reinterpret_cast<__nv_bfloat162*>(hi + idx + 2) = __nv_bfloat162(h2, h3);
    *reinterpret_cast<__nv_bfloat162*>(lo + idx)     = __nv_bfloat162(l0, l1);
    *reinterpret_cast<__nv_bfloat162*>(lo + idx + 2) = __nv_bfloat162(l2, l3);
}

// W [K,N] -> Wt hi/lo [N,K]
__global__ void transpose_split_kernel(const float* __restrict__ W,
                                       __nv_bfloat16* __restrict__ th,
                                       __nv_bfloat16* __restrict__ tl,
                                       int K, int N)
{
    __shared__ float t[32][33];
    const int tx = threadIdx.x, ty = threadIdx.y;
    const int n0 = blockIdx.x * 32, k0 = blockIdx.y * 32;
#pragma unroll
    for (int j = ty; j < 32; j += 8)
        t[j][tx] = W[(size_t)(k0 + j) * N + n0 + tx];
    __syncthreads();
#pragma unroll
    for (int j = ty; j < 32; j += 8) {
        float v = t[tx][j];
        __nv_bfloat16 h, l;
        split1(v, h, l);
        size_t o = (size_t)(n0 + j) * K + k0 + tx;
        th[o] = h;
        tl[o] = l;
    }
}

// ---------------- mma.sync bf16 3-term GEMM ----------------
// C[M,N] = A[M,K] @ Bt[N,K]^T + bias   (Ah*Bh + Ah*Bl + Al*Bh, fp32 acc)
// CTA tile 128x128, BK=32, 8 warps of 64x32, cp.async double buffer.
#define TS 40                          // padded smem row stride (elems)
#define TILE_B (128 * TS * 2)          // 10240 B per tile
#define STAGE_B (4 * TILE_B)           // Ah, Al, Bh, Bl
#define GEMM_SMEM (2 * STAGE_B)        // 81920 B

__global__ __launch_bounds__(256) void gemm_mma_kernel(
    const __nv_bfloat16* __restrict__ Ah, const __nv_bfloat16* __restrict__ Al,
    const __nv_bfloat16* __restrict__ Bh, const __nv_bfloat16* __restrict__ Bl,
    const float* __restrict__ bias, float* __restrict__ C, int N)
{
    extern __shared__ char smem[];
    const uint32_t sbase = smem_u32(smem);
    const int tid = threadIdx.x;
    const int wid = tid >> 5, lane = tid & 31;
    const int m0 = blockIdx.y * 128, n0 = blockIdx.x * 128;
    const int wm = wid >> 2, wn = wid & 3;   // warp tile: rows wm*64, cols wn*32

    const __nv_bfloat16* aB[2] = {Ah + (size_t)m0 * KDIM, Al + (size_t)m0 * KDIM};
    const __nv_bfloat16* bB[2] = {Bh + (size_t)n0 * KDIM, Bl + (size_t)n0 * KDIM};

    float acc[4][4][4];
#pragma unroll
    for (int i = 0; i < 4; i++)
#pragma unroll
        for (int j = 0; j < 4; j++)
#pragma unroll
            for (int v = 0; v < 4; v++) acc[i][j][v] = 0.f;

    const int NC = KDIM / 32;  // 32 chunks

    auto issue = [&](int stage, int c) {
        const int k0 = c * 32;
        const uint32_t sb = sbase + stage * STAGE_B;
#pragma unroll
        for (int t = 0; t < 2; t++) {
#pragma unroll
            for (int i = 0; i < 2; i++) {
                const int cid = tid + 256 * i;
                const int r = cid >> 2, q = cid & 3;
                cp16(sb + t * TILE_B + (r * TS + q * 8) * 2,
                     aB[t] + (size_t)r * KDIM + k0 + q * 8);
                cp16(sb + (2 + t) * TILE_B + (r * TS + q * 8) * 2,
                     bB[t] + (size_t)r * KDIM + k0 + q * 8);
            }
        }
        CP_COMMIT();
    };

    issue(0, 0);

    for (int c = 0; c < NC; c++) {
        const int st = c & 1;
        if (c + 1 < NC) {
            issue((c + 1) & 1, c + 1);
            CP_WAIT(1);
        } else {
            CP_WAIT(0);
        }
        __syncthreads();

        const uint32_t sAh = sbase + st * STAGE_B;
        const uint32_t sAl = sAh + TILE_B;
        const uint32_t sBh = sAh + 2 * TILE_B;
        const uint32_t sBl = sAh + 3 * TILE_B;

        const int rowa = wm * 64 + (lane & 15);
        const int rowb = wn * 32 + (lane & 15);
        const int ko = (lane >> 4) * 8;

#pragma unroll
        for (int kt = 0; kt < 2; kt++) {
            const int k = kt * 16 + ko;
            uint32_t ah[4][4], al[4][4], bh[2][4], bl[2][4];
#pragma unroll
            for (int mt = 0; mt < 4; mt++) {
                ldsm_x4(ah[mt], sAh + ((rowa + mt * 16) * TS + k) * 2);
                ldsm_x4(al[mt], sAl + ((rowa + mt * 16) * TS + k) * 2);
            }
#pragma unroll
            for (int nt = 0; nt < 2; nt++) {
                ldsm_x4(bh[nt], sBh + ((rowb + nt * 16) * TS + k) * 2);
                ldsm_x4(bl[nt], sBl + ((rowb + nt * 16) * TS + k) * 2);
            }
            // B fragment pairing: for n-group h (0: n0-7, 1: n8-15) the mma
            // needs {k0-7, k8-15} = {r[h], r[h+2]} from ldmatrix.x4 on [n][k].
#pragma unroll
            for (int mt = 0; mt < 4; mt++)
#pragma unroll
                for (int nt = 0; nt < 2; nt++)
#pragma unroll
                    for (int h = 0; h < 2; h++) {
                        float* d = acc[mt][nt * 2 + h];
                        mma_bf16(d, ah[mt], bh[nt][h], bh[nt][h + 2]);
                        mma_bf16(d, ah[mt], bl[nt][h], bl[nt][h + 2]);
                        mma_bf16(d, al[mt], bh[nt][h], bh[nt][h + 2]);
                    }
        }
        __syncthreads();
    }

    // epilogue: fragment layout — g=lane>>2 row, tig=lane&3 col pair
    const int g = lane >> 2, tig = lane & 3;
#pragma unroll
    for (int mt = 0; mt < 4; mt++) {
#pragma unroll
        for (int n8 = 0; n8 < 4; n8++) {
            const int col = n0 + wn * 32 + n8 * 8 + tig * 2;
            const float2 bv = *reinterpret_cast<const float2*>(bias + col);
            const int row = m0 + wm * 64 + mt * 16 + g;
            float* d = acc[mt][n8];
            float2 o0 = make_float2(d[0] + bv.x, d[1] + bv.y);
            float2 o1 = make_float2(d[2] + bv.x, d[3] + bv.y);
            *reinterpret_cast<float2*>(C + (size_t)row * N + col) = o0;
            *reinterpret_cast<float2*>(C + (size_t)(row + 8) * N + col) = o1;
        }
    }
}

// ---------------------------------------------------------------------------
// Flash attention (causal), fp32, register-blocked.  (unchanged, validated)
// ---------------------------------------------------------------------------
#define AT_STRIDE 68
#define ATTN_SMEM (3 * 64 * AT_STRIDE * 4)

__global__ __launch_bounds__(256) void attn_kernel(
    const float* __restrict__ qkv, float* __restrict__ y)
{
    extern __shared__ float sm[];
    float* Qs = sm;
    float* Ks = sm + 64 * AT_STRIDE;
    float* Vs = sm + 2 * 64 * AT_STRIDE;

    const int tid = threadIdx.x;
    const int bh = blockIdx.y;
    const int b = bh / N_HEADS;
    const int h = bh % N_HEADS;
    const int qt = blockIdx.x;
    const int q0 = qt * 64;

    const int rs = QKV_N;
    const float* base = qkv + (size_t)b * SEQ * rs + h * HD;
    const float* Qg = base;
    const float* Kg = base + D_MODEL;
    const float* Vg = base + 2 * D_MODEL;

    const int tr = tid >> 4;
    const int tc = tid & 15;
    const int r0 = 4 * tr;

    {
        const int lr = tid >> 2, seg = tid & 3;
        const float* src = Qg + (size_t)(q0 + lr) * rs + seg * 16;
        float* dst = Qs + lr * AT_STRIDE + seg * 16;
#pragma unroll
        for (int i = 0; i < 4; i++)
            *reinterpret_cast<float4*>(dst + 4 * i) =
                *reinterpret_cast<const float4*>(src + 4 * i);
    }

    float m[4], l[4], o[4][4];
#pragma unroll
    for (int i = 0; i < 4; i++) {
        m[i] = -INFINITY; l[i] = 0.f;
#pragma unroll
        for (int d = 0; d < 4; d++) o[i][d] = 0.f;
    }

    const float scale = 0.125f;

    for (int kt = 0; kt <= qt; kt++) {
        const int k0 = kt * 64;
        __syncthreads();
        {
            const int lr = tid >> 2, seg = tid & 3;
            const float* srcK = Kg + (size_t)(k0 + lr) * rs + seg * 16;
            const float* srcV = Vg + (size_t)(k0 + lr) * rs + seg * 16;
            float* dstK = Ks + lr * AT_STRIDE + seg * 16;
            float* dstV = Vs + lr * AT_STRIDE + seg * 16;
#pragma unroll
            for (int i = 0; i < 4; i++) {
                *reinterpret_cast<float4*>(dstK + 4 * i) =
                    *reinterpret_cast<const float4*>(srcK + 4 * i);
                *reinterpret_cast<float4*>(dstV + 4 * i) =
                    *reinterpret_cast<const float4*>(srcV + 4 * i);
            }
        }
        __syncthreads();

        float s[4][4];
#pragma unroll
        for (int i = 0; i < 4; i++)
#pragma unroll
            for (int j = 0; j < 4; j++) s[i][j] = 0.f;

#pragma unroll 4
        for (int kk = 0; kk < 16; kk++) {
            float4 qv[4], kv[4];
#pragma unroll
            for (int i = 0; i < 4; i++)
                qv[i] = *reinterpret_cast<const float4*>(Qs + (r0 + i) * AT_STRIDE + 4 * kk);
#pragma unroll
            for (int j = 0; j < 4; j++)
                kv[j] = *reinterpret_cast<const float4*>(Ks + (tc + 16 * j) * AT_STRIDE + 4 * kk);
#pragma unroll
            for (int i = 0; i < 4; i++)
#pragma unroll
                for (int j = 0; j < 4; j++)
                    s[i][j] += qv[i].x * kv[j].x + qv[i].y * kv[j].y +
                               qv[i].z * kv[j].z + qv[i].w * kv[j].w;
        }

        if (kt == qt) {
#pragma unroll
            for (int i = 0; i < 4; i++) {
                const int qg = q0 + r0 + i;
#pragma unroll
                for (int j = 0; j < 4; j++) {
                    const int kg = k0 + tc + 16 * j;
                    s[i][j] = (kg <= qg) ? s[i][j] * scale : -INFINITY;
                }
            }
        } else {
#pragma unroll
            for (int i = 0; i < 4; i++)
#pragma unroll
                for (int j = 0; j < 4; j++) s[i][j] *= scale;
        }

        float p[4][4];
#pragma unroll
        for (int i = 0; i < 4; i++) {
            float mt = fmaxf(fmaxf(s[i][0], s[i][1]), fmaxf(s[i][2], s[i][3]));
            mt = fmaxf(mt, __shfl_xor_sync(0xffffffffu, mt, 1));
            mt = fmaxf(mt, __shfl_xor_sync(0xffffffffu, mt, 2));
            mt = fmaxf(mt, __shfl_xor_sync(0xffffffffu, mt, 4));
            mt = fmaxf(mt, __shfl_xor_sync(0xffffffffu, mt, 8));
            const float mn = fmaxf(m[i], mt);
            const float corr = __expf(m[i] - mn);
            float ps = 0.f;
#pragma unroll
            for (int j = 0; j < 4; j++) {
                p[i][j] = __expf(s[i][j] - mn);
                ps += p[i][j];
            }
            ps += __shfl_xor_sync(0xffffffffu, ps, 1);
            ps += __shfl_xor_sync(0xffffffffu, ps, 2);
            ps += __shfl_xor_sync(0xffffffffu, ps, 4);
            ps += __shfl_xor_sync(0xffffffffu, ps, 8);
            l[i] = l[i] * corr + ps;
            m[i] = mn;
#pragma unroll
            for (int d = 0; d < 4; d++) o[i][d] *= corr;
        }

        __syncthreads();
#pragma unroll
        for (int j = 0; j < 4; j++) {
            float4 pw = make_float4(p[0][j], p[1][j], p[2][j], p[3][j]);
            *reinterpret_cast<float4*>(Ks + (tc + 16 * j) * AT_STRIDE + r0) = pw;
        }
        __syncthreads();

        const int c0 = 4 * tc;
#pragma unroll 8
        for (int j = 0; j < 64; j++) {
            float4 pv = *reinterpret_cast<const float4*>(Ks + j * AT_STRIDE + r0);
            float4 vv = *reinterpret_cast<const float4*>(Vs + j * AT_STRIDE + c0);
            o[0][0] += pv.x * vv.x; o[0][1] += pv.x * vv.y;
            o[0][2] += pv.x * vv.z; o[0][3] += pv.x * vv.w;
            o[1][0] += pv.y * vv.x; o[1][1] += pv.y * vv.y;
            o[1][2] += pv.y * vv.z; o[1][3] += pv.y * vv.w;
            o[2][0] += pv.z * vv.x; o[2][1] += pv.z * vv.y;
            o[2][2] += pv.z * vv.z; o[2][3] += pv.z * vv.w;
            o[3][0] += pv.w * vv.x; o[3][1] += pv.w * vv.y;
            o[3][2] += pv.w * vv.z; o[3][3] += pv.w * vv.w;
        }
    }

#pragma unroll
    for (int i = 0; i < 4; i++) {
        const float inv = 1.f / l[i];
        float4 ov = make_float4(o[i][0] * inv, o[i][1] * inv,
                                o[i][2] * inv, o[i][3] * inv);
        *reinterpret_cast<float4*>(
            y + ((size_t)b * SEQ + q0 + r0 + i) * D_MODEL + h * HD + 4 * tc) = ov;
    }
}

// ---------------------------------------------------------------------------
extern "C" void kernel_launch(void* const* d_in, const int* in_sizes, int n_in,
                              void* d_out, int out_size)
{
    const float* x      = (const float*)d_in[0];
    const float* W_attn = (const float*)d_in[1];
    const float* b_attn = (const float*)d_in[2];
    const float* W_proj = (const float*)d_in[3];
    const float* b_proj = (const float*)d_in[4];
    float* out = (float*)d_out;

    float *qkv, *y;
    __nv_bfloat16 *xh, *xl, *yh, *yl, *wah, *wal, *wph, *wpl;
    cudaGetSymbolAddress((void**)&qkv, g_qkv);
    cudaGetSymbolAddress((void**)&y, g_y);
    cudaGetSymbolAddress((void**)&xh, g_x_hi);
    cudaGetSymbolAddress((void**)&xl, g_x_lo);
    cudaGetSymbolAddress((void**)&yh, g_y_hi);
    cudaGetSymbolAddress((void**)&yl, g_y_lo);
    cudaGetSymbolAddress((void**)&wah, g_wat_hi);
    cudaGetSymbolAddress((void**)&wal, g_wat_lo);
    cudaGetSymbolAddress((void**)&wph, g_wpt_hi);
    cudaGetSymbolAddress((void**)&wpl, g_wpt_lo);

    cudaFuncSetAttribute(attn_kernel,
                         cudaFuncAttributeMaxDynamicSharedMemorySize, ATTN_SMEM);
    cudaFuncSetAttribute(gemm_mma_kernel,
                         cudaFuncAttributeMaxDynamicSharedMemorySize, GEMM_SMEM);

    const int NX = M_TOTAL * KDIM;

    // prep: split x, transpose+split weights
    split_kernel<<<NX / (256 * 4), 256>>>(x, xh, xl, NX);
    transpose_split_kernel<<<dim3(QKV_N / 32, KDIM / 32), dim3(32, 8)>>>(
        W_attn, wah, wal, KDIM, QKV_N);
    transpose_split_kernel<<<dim3(D_MODEL / 32, KDIM / 32), dim3(32, 8)>>>(
        W_proj, wph, wpl, KDIM, D_MODEL);

    // 1) qkv = x @ W_attn + b_attn (tensor cores via mma.sync)
    gemm_mma_kernel<<<dim3(QKV_N / 128, M_TOTAL / 128), 256, GEMM_SMEM>>>(
        xh, xl, wah, wal, b_attn, qkv, QKV_N);

    // 2) flash attention -> y
    attn_kernel<<<dim3(SEQ / 64, BATCH * N_HEADS), 256, ATTN_SMEM>>>(qkv, y);

    // 3) out = y @ W_proj + b_proj
    split_kernel<<<NX / (256 * 4), 256>>>(y, yh, yl, NX);
    gemm_mma_kernel<<<dim3(D_MODEL / 128, M_TOTAL / 128), 256, GEMM_SMEM>>>(
        yh, yl, wph, wpl, b_proj, out, D_MODEL);
}

// round 7
// speedup vs baseline: 1.6430x; 1.6430x over previous
#include <cuda_runtime.h>
#include <cuda_bf16.h>
#include <math.h>
#include <stdint.h>

#define D_MODEL 1024
#define N_HEADS 16
#define HD 64
#define BATCH 2
#define SEQ 2048
#define M_TOTAL (BATCH * SEQ)   // 4096
#define QKV_N (3 * D_MODEL)     // 3072
#define KDIM 1024

// ---------------- scratch (device globals; allocation-free) ----------------
__device__ float g_qkv[(size_t)M_TOTAL * QKV_N];
__device__ float g_y[(size_t)M_TOTAL * D_MODEL];

__device__ __align__(256) __nv_bfloat16 g_x_hi[(size_t)M_TOTAL * KDIM];
__device__ __align__(256) __nv_bfloat16 g_x_lo[(size_t)M_TOTAL * KDIM];
__device__ __align__(256) __nv_bfloat16 g_y_hi[(size_t)M_TOTAL * KDIM];
__device__ __align__(256) __nv_bfloat16 g_y_lo[(size_t)M_TOTAL * KDIM];
__device__ __align__(256) __nv_bfloat16 g_qkv_hi[(size_t)M_TOTAL * QKV_N];
__device__ __align__(256) __nv_bfloat16 g_qkv_lo[(size_t)M_TOTAL * QKV_N];
__device__ __align__(256) __nv_bfloat16 g_wat_hi[(size_t)QKV_N * KDIM];
__device__ __align__(256) __nv_bfloat16 g_wat_lo[(size_t)QKV_N * KDIM];
__device__ __align__(256) __nv_bfloat16 g_wpt_hi[(size_t)D_MODEL * KDIM];
__device__ __align__(256) __nv_bfloat16 g_wpt_lo[(size_t)D_MODEL * KDIM];

// ---------------- helpers ----------------
__device__ __forceinline__ uint32_t smem_u32(const void* p) {
    uint32_t a;
    asm("{ .reg .u64 t; cvta.to.shared.u64 t, %1; cvt.u32.u64 %0, t; }"
        : "=r"(a) : "l"(p));
    return a;
}

__device__ __forceinline__ void cp16(uint32_t dst, const void* src) {
    asm volatile("cp.async.cg.shared.global [%0], [%1], 16;" :: "r"(dst), "l"(src));
}
#define CP_COMMIT() asm volatile("cp.async.commit_group;" ::: "memory")
#define CP_WAIT(n)  asm volatile("cp.async.wait_group %0;" :: "n"(n) : "memory")

__device__ __forceinline__ void ldsm_x4(uint32_t* r, uint32_t addr) {
    asm volatile("ldmatrix.sync.aligned.m8n8.x4.shared.b16 {%0,%1,%2,%3}, [%4];"
        : "=r"(r[0]), "=r"(r[1]), "=r"(r[2]), "=r"(r[3]) : "r"(addr));
}
__device__ __forceinline__ void ldsm_x4_t(uint32_t* r, uint32_t addr) {
    asm volatile("ldmatrix.sync.aligned.m8n8.x4.trans.shared.b16 {%0,%1,%2,%3}, [%4];"
        : "=r"(r[0]), "=r"(r[1]), "=r"(r[2]), "=r"(r[3]) : "r"(addr));
}

__device__ __forceinline__ void mma_bf16(float* d, const uint32_t* a,
                                         uint32_t b0, uint32_t b1) {
    asm volatile(
        "mma.sync.aligned.m16n8k16.row.col.f32.bf16.bf16.f32 "
        "{%0,%1,%2,%3}, {%4,%5,%6,%7}, {%8,%9}, {%0,%1,%2,%3};"
        : "+f"(d[0]), "+f"(d[1]), "+f"(d[2]), "+f"(d[3])
        : "r"(a[0]), "r"(a[1]), "r"(a[2]), "r"(a[3]), "r"(b0), "r"(b1));
}

// ---------------- conversion kernels ----------------
__device__ __forceinline__ void split1(float v, __nv_bfloat16& h, __nv_bfloat16& l) {
    h = __float2bfloat16(v);
    l = __float2bfloat16(v - __bfloat162float(h));
}

__global__ void split_kernel(const float* __restrict__ in,
                             __nv_bfloat16* __restrict__ hi,
                             __nv_bfloat16* __restrict__ lo, int n)
{
    int idx = (blockIdx.x * blockDim.x + threadIdx.x) * 4;
    if (idx >= n) return;
    float4 v = *reinterpret_cast<const float4*>(in + idx);
    __nv_bfloat16 h0, h1, h2, h3, l0, l1, l2, l3;
    split1(v.x, h0, l0); split1(v.y, h1, l1);
    split1(v.z, h2, l2); split1(v.w, h3, l3);
    *reinterpret_cast<__nv_bfloat162*>(hi + idx)     = __nv_bfloat162(h0, h1);
    *reinterpret_cast<__nv_bfloat162*>(hi + idx + 2) = __nv_bfloat162(h2, h3);
    *reinterpret_cast<__nv_bfloat162*>(lo + idx)     = __nv_bfloat162(l0, l1);
    *reinterpret_cast<__nv_bfloat162*>(lo + idx + 2) = __nv_bfloat162(l2, l3);
}

__global__ void transpose_split_kernel(const float* __restrict__ W,
                                       __nv_bfloat16* __restrict__ th,
                                       __nv_bfloat16* __restrict__ tl,
                                       int K, int N)
{
    __shared__ float t[32][33];
    const int tx = threadIdx.x, ty = threadIdx.y;
    const int n0 = blockIdx.x * 32, k0 = blockIdx.y * 32;
#pragma unroll
    for (int j = ty; j < 32; j += 8)
        t[j][tx] = W[(size_t)(k0 + j) * N + n0 + tx];
    __syncthreads();
#pragma unroll
    for (int j = ty; j < 32; j += 8) {
        float v = t[tx][j];
        __nv_bfloat16 h, l;
        split1(v, h, l);
        size_t o = (size_t)(n0 + j) * K + k0 + tx;
        th[o] = h;
        tl[o] = l;
    }
}

// ---------------- mma.sync bf16 3-term GEMM (validated R6) ----------------
#define TS 40
#define TILE_B (128 * TS * 2)
#define STAGE_B (4 * TILE_B)
#define GEMM_SMEM (2 * STAGE_B)

__global__ __launch_bounds__(256) void gemm_mma_kernel(
    const __nv_bfloat16* __restrict__ Ah, const __nv_bfloat16* __restrict__ Al,
    const __nv_bfloat16* __restrict__ Bh, const __nv_bfloat16* __restrict__ Bl,
    const float* __restrict__ bias, float* __restrict__ C, int N)
{
    extern __shared__ char smem[];
    const uint32_t sbase = smem_u32(smem);
    const int tid = threadIdx.x;
    const int wid = tid >> 5, lane = tid & 31;
    const int m0 = blockIdx.y * 128, n0 = blockIdx.x * 128;
    const int wm = wid >> 2, wn = wid & 3;

    const __nv_bfloat16* aB[2] = {Ah + (size_t)m0 * KDIM, Al + (size_t)m0 * KDIM};
    const __nv_bfloat16* bB[2] = {Bh + (size_t)n0 * KDIM, Bl + (size_t)n0 * KDIM};

    float acc[4][4][4];
#pragma unroll
    for (int i = 0; i < 4; i++)
#pragma unroll
        for (int j = 0; j < 4; j++)
#pragma unroll
            for (int v = 0; v < 4; v++) acc[i][j][v] = 0.f;

    const int NC = KDIM / 32;

    auto issue = [&](int stage, int c) {
        const int k0 = c * 32;
        const uint32_t sb = sbase + stage * STAGE_B;
#pragma unroll
        for (int t = 0; t < 2; t++) {
#pragma unroll
            for (int i = 0; i < 2; i++) {
                const int cid = tid + 256 * i;
                const int r = cid >> 2, q = cid & 3;
                cp16(sb + t * TILE_B + (r * TS + q * 8) * 2,
                     aB[t] + (size_t)r * KDIM + k0 + q * 8);
                cp16(sb + (2 + t) * TILE_B + (r * TS + q * 8) * 2,
                     bB[t] + (size_t)r * KDIM + k0 + q * 8);
            }
        }
        CP_COMMIT();
    };

    issue(0, 0);

    for (int c = 0; c < NC; c++) {
        const int st = c & 1;
        if (c + 1 < NC) {
            issue((c + 1) & 1, c + 1);
            CP_WAIT(1);
        } else {
            CP_WAIT(0);
        }
        __syncthreads();

        const uint32_t sAh = sbase + st * STAGE_B;
        const uint32_t sAl = sAh + TILE_B;
        const uint32_t sBh = sAh + 2 * TILE_B;
        const uint32_t sBl = sAh + 3 * TILE_B;

        const int rowa = wm * 64 + (lane & 15);
        const int rowb = wn * 32 + (lane & 15);
        const int ko = (lane >> 4) * 8;

#pragma unroll
        for (int kt = 0; kt < 2; kt++) {
            const int k = kt * 16 + ko;
            uint32_t ah[4][4], al[4][4], bh[2][4], bl[2][4];
#pragma unroll
            for (int mt = 0; mt < 4; mt++) {
                ldsm_x4(ah[mt], sAh + ((rowa + mt * 16) * TS + k) * 2);
                ldsm_x4(al[mt], sAl + ((rowa + mt * 16) * TS + k) * 2);
            }
#pragma unroll
            for (int nt = 0; nt < 2; nt++) {
                ldsm_x4(bh[nt], sBh + ((rowb + nt * 16) * TS + k) * 2);
                ldsm_x4(bl[nt], sBl + ((rowb + nt * 16) * TS + k) * 2);
            }
#pragma unroll
            for (int mt = 0; mt < 4; mt++)
#pragma unroll
                for (int nt = 0; nt < 2; nt++)
#pragma unroll
                    for (int h = 0; h < 2; h++) {
                        float* d = acc[mt][nt * 2 + h];
                        mma_bf16(d, ah[mt], bh[nt][h], bh[nt][h + 2]);
                        mma_bf16(d, ah[mt], bl[nt][h], bl[nt][h + 2]);
                        mma_bf16(d, al[mt], bh[nt][h], bh[nt][h + 2]);
                    }
        }
        __syncthreads();
    }

    const int g = lane >> 2, tig = lane & 3;
#pragma unroll
    for (int mt = 0; mt < 4; mt++) {
#pragma unroll
        for (int n8 = 0; n8 < 4; n8++) {
            const int col = n0 + wn * 32 + n8 * 8 + tig * 2;
            const float2 bv = *reinterpret_cast<const float2*>(bias + col);
            const int row = m0 + wm * 64 + mt * 16 + g;
            float* d = acc[mt][n8];
            float2 o0 = make_float2(d[0] + bv.x, d[1] + bv.y);
            float2 o1 = make_float2(d[2] + bv.x, d[3] + bv.y);
            *reinterpret_cast<float2*>(C + (size_t)row * N + col) = o0;
            *reinterpret_cast<float2*>(C + (size_t)(row + 8) * N + col) = o1;
        }
    }
}

// ---------------- mma.sync flash attention (causal) ----------------
// q-tile 64, k-tile 64, 4 warps (16 q-rows each). 3-term bf16 split for
// S = Q K^T and O += P V, fp32 accumulators + online softmax in fragments.
// K/V hi/lo double-buffered via cp.async. P stays in registers.
#define AS 72                      // bf16 row stride in smem
#define ATILE_B (64 * AS * 2)      // 9216 B per 64x64 bf16 tile
#define A_STAGE0 (2 * ATILE_B)     // after Qh, Ql
#define A_STAGE_B (4 * ATILE_B)    // Kh, Kl, Vh, Vl
#define ATTN_SMEM (A_STAGE0 + 2 * A_STAGE_B)  // 92160 B

__global__ __launch_bounds__(128) void attn_mma_kernel(
    const __nv_bfloat16* __restrict__ qkvh,
    const __nv_bfloat16* __restrict__ qkvl,
    float* __restrict__ y)
{
    extern __shared__ char smem[];
    const uint32_t sb = smem_u32(smem);
    const int tid = threadIdx.x;
    const int wid = tid >> 5, lane = tid & 31;
    const int g = lane >> 2, tig = lane & 3;

    const int bh = blockIdx.y;
    const int b = bh >> 4, h = bh & 15;
    const int qt = (int)gridDim.x - 1 - (int)blockIdx.x;  // longest first
    const int q0 = qt * 64;

    const size_t rowbase = (size_t)b * SEQ * QKV_N + h * HD;  // + t*QKV_N
    const uint32_t sQh = sb, sQl = sb + ATILE_B;

    // ---- prologue: Q + K/V stage 0 ----
    {
#pragma unroll
        for (int i = 0; i < 4; i++) {
            const int cid = tid + 128 * i;
            const int r = cid >> 3, q = cid & 7;
            const size_t go = rowbase + (size_t)(q0 + r) * QKV_N + q * 8;
            cp16(sQh + (r * AS + q * 8) * 2, qkvh + go);
            cp16(sQl + (r * AS + q * 8) * 2, qkvl + go);
        }
    }
    auto issueKV = [&](int stage, int kt) {
        const int k0 = kt * 64;
        const uint32_t sbK = sb + A_STAGE0 + stage * A_STAGE_B;
#pragma unroll
        for (int i = 0; i < 4; i++) {
            const int cid = tid + 128 * i;
            const int r = cid >> 3, q = cid & 7;
            const size_t gK = rowbase + (size_t)(k0 + r) * QKV_N + D_MODEL + q * 8;
            const size_t gV = gK + D_MODEL;
            const uint32_t so = (r * AS + q * 8) * 2;
            cp16(sbK + so, qkvh + gK);
            cp16(sbK + ATILE_B + so, qkvl + gK);
            cp16(sbK + 2 * ATILE_B + so, qkvh + gV);
            cp16(sbK + 3 * ATILE_B + so, qkvl + gV);
        }
        CP_COMMIT();
    };
    issueKV(0, 0);

    // state
    float m[2], l[2], oacc[8][4];
    m[0] = m[1] = -INFINITY;
    l[0] = l[1] = 0.f;
#pragma unroll
    for (int t = 0; t < 8; t++)
#pragma unroll
        for (int v = 0; v < 4; v++) oacc[t][v] = 0.f;

    uint32_t qh[4][4], ql[4][4];
    bool qloaded = false;
    const float scale = 0.125f;
    const int rowa = wid * 16 + (lane & 15);
    const int ko = (lane >> 4) * 8;

    for (int kt = 0; kt <= qt; kt++) {
        if (kt < qt) {
            issueKV((kt + 1) & 1, kt + 1);
            CP_WAIT(1);
        } else {
            CP_WAIT(0);
        }
        __syncthreads();

        const uint32_t sK = sb + A_STAGE0 + (kt & 1) * A_STAGE_B;
        const uint32_t sKh = sK, sKl = sK + ATILE_B;
        const uint32_t sVh = sK + 2 * ATILE_B, sVl = sK + 3 * ATILE_B;

        if (!qloaded) {
#pragma unroll
            for (int kc = 0; kc < 4; kc++) {
                ldsm_x4(qh[kc], sQh + (rowa * AS + kc * 16 + ko) * 2);
                ldsm_x4(ql[kc], sQl + (rowa * AS + kc * 16 + ko) * 2);
            }
            qloaded = true;
        }

        // ---- S = Q K^T (3-term) ----
        float sacc[8][4];
#pragma unroll
        for (int t = 0; t < 8; t++)
#pragma unroll
            for (int v = 0; v < 4; v++) sacc[t][v] = 0.f;

#pragma unroll
        for (int kc = 0; kc < 4; kc++) {
#pragma unroll
            for (int nt = 0; nt < 4; nt++) {
                uint32_t kbh[4], kbl[4];
                const uint32_t ka = ((nt * 16 + (lane & 15)) * AS + kc * 16 + ko) * 2;
                ldsm_x4(kbh, sKh + ka);
                ldsm_x4(kbl, sKl + ka);
#pragma unroll
                for (int hh = 0; hh < 2; hh++) {
                    float* d = sacc[nt * 2 + hh];
                    mma_bf16(d, qh[kc], kbh[hh], kbh[hh + 2]);
                    mma_bf16(d, qh[kc], kbl[hh], kbl[hh + 2]);
                    mma_bf16(d, ql[kc], kbh[hh], kbh[hh + 2]);
                }
            }
        }

        // ---- scale + causal mask ----
        const int k0 = kt * 64;
        if (kt == qt) {
#pragma unroll
            for (int t = 0; t < 8; t++)
#pragma unroll
                for (int v = 0; v < 4; v++) {
                    const int kg = k0 + t * 8 + 2 * tig + (v & 1);
                    const int qg = q0 + wid * 16 + g + (v >> 1) * 8;
                    sacc[t][v] = (kg <= qg) ? sacc[t][v] * scale : -INFINITY;
                }
        } else {
#pragma unroll
            for (int t = 0; t < 8; t++)
#pragma unroll
                for (int v = 0; v < 4; v++) sacc[t][v] *= scale;
        }

        // ---- online softmax (rows g and g+8; quad = lanes sharing g) ----
#pragma unroll
        for (int rh = 0; rh < 2; rh++) {
            float mt = -INFINITY;
#pragma unroll
            for (int t = 0; t < 8; t++)
                mt = fmaxf(mt, fmaxf(sacc[t][rh * 2], sacc[t][rh * 2 + 1]));
            mt = fmaxf(mt, __shfl_xor_sync(0xffffffffu, mt, 1));
            mt = fmaxf(mt, __shfl_xor_sync(0xffffffffu, mt, 2));
            const float mn = fmaxf(m[rh], mt);
            const float corr = __expf(m[rh] - mn);
            m[rh] = mn;
            float ps = 0.f;
#pragma unroll
            for (int t = 0; t < 8; t++) {
                float p0 = __expf(sacc[t][rh * 2] - mn);
                float p1 = __expf(sacc[t][rh * 2 + 1] - mn);
                sacc[t][rh * 2] = p0;
                sacc[t][rh * 2 + 1] = p1;
                ps += p0 + p1;
            }
            ps += __shfl_xor_sync(0xffffffffu, ps, 1);
            ps += __shfl_xor_sync(0xffffffffu, ps, 2);
            l[rh] = l[rh] * corr + ps;
#pragma unroll
            for (int t = 0; t < 8; t++) {
                oacc[t][rh * 2] *= corr;
                oacc[t][rh * 2 + 1] *= corr;
            }
        }

        // ---- convert P to bf16 hi/lo in registers (A-fragment layout) ----
        uint32_t ph[8][2], pl[8][2];
#pragma unroll
        for (int t = 0; t < 8; t++)
#pragma unroll
            for (int rh = 0; rh < 2; rh++) {
                float2 f = make_float2(sacc[t][rh * 2], sacc[t][rh * 2 + 1]);
                __nv_bfloat162 h2 = __floats2bfloat162_rn(f.x, f.y);
                float2 bk = __bfloat1622float2(h2);
                __nv_bfloat162 l2 = __floats2bfloat162_rn(f.x - bk.x, f.y - bk.y);
                ph[t][rh] = *reinterpret_cast<uint32_t*>(&h2);
                pl[t][rh] = *reinterpret_cast<uint32_t*>(&l2);
            }

        // ---- O += P V (3-term), V via ldmatrix.trans on [j][d] ----
        const int vrow = ((lane >> 4) & 1) * 8 + (lane & 7);
        const int vcol = ((lane >> 3) & 1) * 8;
#pragma unroll
        for (int jc = 0; jc < 4; jc++) {
            uint32_t pa_h[4] = {ph[2 * jc][0], ph[2 * jc][1],
                                ph[2 * jc + 1][0], ph[2 * jc + 1][1]};
            uint32_t pa_l[4] = {pl[2 * jc][0], pl[2 * jc][1],
                                pl[2 * jc + 1][0], pl[2 * jc + 1][1]};
#pragma unroll
            for (int dt = 0; dt < 4; dt++) {
                uint32_t vbh[4], vbl[4];
                const uint32_t va = ((jc * 16 + vrow) * AS + dt * 16 + vcol) * 2;
                ldsm_x4_t(vbh, sVh + va);
                ldsm_x4_t(vbl, sVl + va);
#pragma unroll
                for (int hh = 0; hh < 2; hh++) {
                    float* d = oacc[dt * 2 + hh];
                    mma_bf16(d, pa_h, vbh[hh], vbh[hh + 2]);
                    mma_bf16(d, pa_h, vbl[hh], vbl[hh + 2]);
                    mma_bf16(d, pa_l, vbh[hh], vbh[hh + 2]);
                }
            }
        }
        __syncthreads();  // done with this K/V stage before it is re-filled
    }

    // ---- epilogue ----
    const float inv0 = 1.f / l[0], inv1 = 1.f / l[1];
    const int row0 = q0 + wid * 16 + g;
#pragma unroll
    for (int t = 0; t < 8; t++) {
        const int col = h * HD + t * 8 + 2 * tig;
        float2 o0 = make_float2(oacc[t][0] * inv0, oacc[t][1] * inv0);
        float2 o1 = make_float2(oacc[t][2] * inv1, oacc[t][3] * inv1);
        *reinterpret_cast<float2*>(
            y + ((size_t)b * SEQ + row0) * D_MODEL + col) = o0;
        *reinterpret_cast<float2*>(
            y + ((size_t)b * SEQ + row0 + 8) * D_MODEL + col) = o1;
    }
}

// ---------------------------------------------------------------------------
extern "C" void kernel_launch(void* const* d_in, const int* in_sizes, int n_in,
                              void* d_out, int out_size)
{
    const float* x      = (const float*)d_in[0];
    const float* W_attn = (const float*)d_in[1];
    const float* b_attn = (const float*)d_in[2];
    const float* W_proj = (const float*)d_in[3];
    const float* b_proj = (const float*)d_in[4];
    float* out = (float*)d_out;

    float *qkv, *y;
    __nv_bfloat16 *xh, *xl, *yh, *yl, *qvh, *qvl, *wah, *wal, *wph, *wpl;
    cudaGetSymbolAddress((void**)&qkv, g_qkv);
    cudaGetSymbolAddress((void**)&y, g_y);
    cudaGetSymbolAddress((void**)&xh, g_x_hi);
    cudaGetSymbolAddress((void**)&xl, g_x_lo);
    cudaGetSymbolAddress((void**)&yh, g_y_hi);
    cudaGetSymbolAddress((void**)&yl, g_y_lo);
    cudaGetSymbolAddress((void**)&qvh, g_qkv_hi);
    cudaGetSymbolAddress((void**)&qvl, g_qkv_lo);
    cudaGetSymbolAddress((void**)&wah, g_wat_hi);
    cudaGetSymbolAddress((void**)&wal, g_wat_lo);
    cudaGetSymbolAddress((void**)&wph, g_wpt_hi);
    cudaGetSymbolAddress((void**)&wpl, g_wpt_lo);

    cudaFuncSetAttribute(gemm_mma_kernel,
                         cudaFuncAttributeMaxDynamicSharedMemorySize, GEMM_SMEM);
    cudaFuncSetAttribute(attn_mma_kernel,
                         cudaFuncAttributeMaxDynamicSharedMemorySize, ATTN_SMEM);

    const int NX = M_TOTAL * KDIM;
    const int NQ = M_TOTAL * QKV_N;

    // prep
    split_kernel<<<NX / (256 * 4), 256>>>(x, xh, xl, NX);
    transpose_split_kernel<<<dim3(QKV_N / 32, KDIM / 32), dim3(32, 8)>>>(
        W_attn, wah, wal, KDIM, QKV_N);
    transpose_split_kernel<<<dim3(D_MODEL / 32, KDIM / 32), dim3(32, 8)>>>(
        W_proj, wph, wpl, KDIM, D_MODEL);

    // 1) qkv = x @ W_attn + b_attn
    gemm_mma_kernel<<<dim3(QKV_N / 128, M_TOTAL / 128), 256, GEMM_SMEM>>>(
        xh, xl, wah, wal, b_attn, qkv, QKV_N);

    // 2) split qkv -> bf16 hi/lo for tensor-core attention
    split_kernel<<<NQ / (256 * 4), 256>>>(qkv, qvh, qvl, NQ);

    // 3) flash attention (mma.sync) -> y
    attn_mma_kernel<<<dim3(SEQ / 64, BATCH * N_HEADS), 128, ATTN_SMEM>>>(
        qvh, qvl, y);

    // 4) out = y @ W_proj + b_proj
    split_kernel<<<NX / (256 * 4), 256>>>(y, yh, yl, NX);
    gemm_mma_kernel<<<dim3(D_MODEL / 128, M_TOTAL / 128), 256, GEMM_SMEM>>>(
        yh, yl, wph, wpl, b_proj, out, D_MODEL);
}

// round 8
// speedup vs baseline: 1.6584x; 1.0093x over previous
#include <cuda_runtime.h>
#include <cuda_bf16.h>
#include <math.h>
#include <stdint.h>

#define D_MODEL 1024
#define N_HEADS 16
#define HD 64
#define BATCH 2
#define SEQ 2048
#define M_TOTAL (BATCH * SEQ)   // 4096
#define QKV_N (3 * D_MODEL)     // 3072
#define KDIM 1024

// ---------------- scratch (device globals; allocation-free) ----------------
__device__ __align__(256) __nv_bfloat16 g_x_hi[(size_t)M_TOTAL * KDIM];
__device__ __align__(256) __nv_bfloat16 g_x_lo[(size_t)M_TOTAL * KDIM];
__device__ __align__(256) __nv_bfloat16 g_y_hi[(size_t)M_TOTAL * KDIM];
__device__ __align__(256) __nv_bfloat16 g_y_lo[(size_t)M_TOTAL * KDIM];
__device__ __align__(256) __nv_bfloat16 g_qkv_hi[(size_t)M_TOTAL * QKV_N];
__device__ __align__(256) __nv_bfloat16 g_qkv_lo[(size_t)M_TOTAL * QKV_N];
__device__ __align__(256) __nv_bfloat16 g_wat_hi[(size_t)QKV_N * KDIM];
__device__ __align__(256) __nv_bfloat16 g_wat_lo[(size_t)QKV_N * KDIM];
__device__ __align__(256) __nv_bfloat16 g_wpt_hi[(size_t)D_MODEL * KDIM];
__device__ __align__(256) __nv_bfloat16 g_wpt_lo[(size_t)D_MODEL * KDIM];

// ---------------- helpers ----------------
__device__ __forceinline__ uint32_t smem_u32(const void* p) {
    uint32_t a;
    asm("{ .reg .u64 t; cvta.to.shared.u64 t, %1; cvt.u32.u64 %0, t; }"
        : "=r"(a) : "l"(p));
    return a;
}

__device__ __forceinline__ void cp16(uint32_t dst, const void* src) {
    asm volatile("cp.async.cg.shared.global [%0], [%1], 16;" :: "r"(dst), "l"(src));
}
#define CP_COMMIT() asm volatile("cp.async.commit_group;" ::: "memory")
#define CP_WAIT0()  asm volatile("cp.async.wait_group 0;" ::: "memory")

__device__ __forceinline__ void ldsm_x4(uint32_t* r, uint32_t addr) {
    asm volatile("ldmatrix.sync.aligned.m8n8.x4.shared.b16 {%0,%1,%2,%3}, [%4];"
        : "=r"(r[0]), "=r"(r[1]), "=r"(r[2]), "=r"(r[3]) : "r"(addr));
}
__device__ __forceinline__ void ldsm_x4_t(uint32_t* r, uint32_t addr) {
    asm volatile("ldmatrix.sync.aligned.m8n8.x4.trans.shared.b16 {%0,%1,%2,%3}, [%4];"
        : "=r"(r[0]), "=r"(r[1]), "=r"(r[2]), "=r"(r[3]) : "r"(addr));
}

__device__ __forceinline__ void mma_bf16(float* d, const uint32_t* a,
                                         uint32_t b0, uint32_t b1) {
    asm volatile(
        "mma.sync.aligned.m16n8k16.row.col.f32.bf16.bf16.f32 "
        "{%0,%1,%2,%3}, {%4,%5,%6,%7}, {%8,%9}, {%0,%1,%2,%3};"
        : "+f"(d[0]), "+f"(d[1]), "+f"(d[2]), "+f"(d[3])
        : "r"(a[0]), "r"(a[1]), "r"(a[2]), "r"(a[3]), "r"(b0), "r"(b1));
}

// ---------------- conversion kernels ----------------
__device__ __forceinline__ void split1(float v, __nv_bfloat16& h, __nv_bfloat16& l) {
    h = __float2bfloat16(v);
    l = __float2bfloat16(v - __bfloat162float(h));
}

__global__ void split_kernel(const float* __restrict__ in,
                             __nv_bfloat16* __restrict__ hi,
                             __nv_bfloat16* __restrict__ lo, int n)
{
    int idx = (blockIdx.x * blockDim.x + threadIdx.x) * 4;
    if (idx >= n) return;
    float4 v = *reinterpret_cast<const float4*>(in + idx);
    __nv_bfloat16 h0, h1, h2, h3, l0, l1, l2, l3;
    split1(v.x, h0, l0); split1(v.y, h1, l1);
    split1(v.z, h2, l2); split1(v.w, h3, l3);
    *reinterpret_cast<__nv_bfloat162*>(hi + idx)     = __nv_bfloat162(h0, h1);
    *reinterpret_cast<__nv_bfloat162*>(hi + idx + 2) = __nv_bfloat162(h2, h3);
    *reinterpret_cast<__nv_bfloat162*>(lo + idx)     = __nv_bfloat162(l0, l1);
    *reinterpret_cast<__nv_bfloat162*>(lo + idx + 2) = __nv_bfloat162(l2, l3);
}

__global__ void transpose_split_kernel(const float* __restrict__ W,
                                       __nv_bfloat16* __restrict__ th,
                                       __nv_bfloat16* __restrict__ tl,
                                       int K, int N)
{
    __shared__ float t[32][33];
    const int tx = threadIdx.x, ty = threadIdx.y;
    const int n0 = blockIdx.x * 32, k0 = blockIdx.y * 32;
#pragma unroll
    for (int j = ty; j < 32; j += 8)
        t[j][tx] = W[(size_t)(k0 + j) * N + n0 + tx];
    __syncthreads();
#pragma unroll
    for (int j = ty; j < 32; j += 8) {
        float v = t[tx][j];
        __nv_bfloat16 h, l;
        split1(v, h, l);
        size_t o = (size_t)(n0 + j) * K + k0 + tx;
        th[o] = h;
        tl[o] = l;
    }
}

// ---------------- mma.sync bf16 3-term GEMM ----------------
// C[M,N] = A[M,K] @ Bt[N,K]^T + bias (Ah*Bh + Ah*Bl + Al*Bh, fp32 acc)
// 2-stage cp.async, ONE barrier per chunk (wait -> barrier -> issue -> compute).
// SPLIT_OUT: write bf16 hi/lo split instead of fp32.
#define TS 40
#define TILE_B (128 * TS * 2)
#define STAGE_B (4 * TILE_B)
#define GEMM_SMEM (2 * STAGE_B)

template <bool SPLIT_OUT>
__global__ __launch_bounds__(256) void gemm_mma_kernel(
    const __nv_bfloat16* __restrict__ Ah, const __nv_bfloat16* __restrict__ Al,
    const __nv_bfloat16* __restrict__ Bh, const __nv_bfloat16* __restrict__ Bl,
    const float* __restrict__ bias, float* __restrict__ C,
    __nv_bfloat16* __restrict__ Ch, __nv_bfloat16* __restrict__ Cl, int N)
{
    extern __shared__ char smem[];
    const uint32_t sbase = smem_u32(smem);
    const int tid = threadIdx.x;
    const int wid = tid >> 5, lane = tid & 31;
    const int m0 = blockIdx.y * 128, n0 = blockIdx.x * 128;
    const int wm = wid >> 2, wn = wid & 3;

    const __nv_bfloat16* aB[2] = {Ah + (size_t)m0 * KDIM, Al + (size_t)m0 * KDIM};
    const __nv_bfloat16* bB[2] = {Bh + (size_t)n0 * KDIM, Bl + (size_t)n0 * KDIM};

    float acc[4][4][4];
#pragma unroll
    for (int i = 0; i < 4; i++)
#pragma unroll
        for (int j = 0; j < 4; j++)
#pragma unroll
            for (int v = 0; v < 4; v++) acc[i][j][v] = 0.f;

    const int NC = KDIM / 32;

    auto issue = [&](int stage, int c) {
        const int k0 = c * 32;
        const uint32_t sb = sbase + stage * STAGE_B;
#pragma unroll
        for (int t = 0; t < 2; t++) {
#pragma unroll
            for (int i = 0; i < 2; i++) {
                const int cid = tid + 256 * i;
                const int r = cid >> 2, q = cid & 3;
                cp16(sb + t * TILE_B + (r * TS + q * 8) * 2,
                     aB[t] + (size_t)r * KDIM + k0 + q * 8);
                cp16(sb + (2 + t) * TILE_B + (r * TS + q * 8) * 2,
                     bB[t] + (size_t)r * KDIM + k0 + q * 8);
            }
        }
        CP_COMMIT();
    };

    issue(0, 0);

    for (int c = 0; c < NC; c++) {
        CP_WAIT0();          // stage c data resident
        __syncthreads();     // all warps done with stage (c-1) reads
        if (c + 1 < NC) issue((c + 1) & 1, c + 1);  // overlaps compute below

        const int st = c & 1;
        const uint32_t sAh = sbase + st * STAGE_B;
        const uint32_t sAl = sAh + TILE_B;
        const uint32_t sBh = sAh + 2 * TILE_B;
        const uint32_t sBl = sAh + 3 * TILE_B;

        const int rowa = wm * 64 + (lane & 15);
        const int rowb = wn * 32 + (lane & 15);
        const int ko = (lane >> 4) * 8;

#pragma unroll
        for (int kt = 0; kt < 2; kt++) {
            const int k = kt * 16 + ko;
            uint32_t ah[4][4], al[4][4], bh[2][4], bl[2][4];
#pragma unroll
            for (int mt = 0; mt < 4; mt++) {
                ldsm_x4(ah[mt], sAh + ((rowa + mt * 16) * TS + k) * 2);
                ldsm_x4(al[mt], sAl + ((rowa + mt * 16) * TS + k) * 2);
            }
#pragma unroll
            for (int nt = 0; nt < 2; nt++) {
                ldsm_x4(bh[nt], sBh + ((rowb + nt * 16) * TS + k) * 2);
                ldsm_x4(bl[nt], sBl + ((rowb + nt * 16) * TS + k) * 2);
            }
#pragma unroll
            for (int mt = 0; mt < 4; mt++)
#pragma unroll
                for (int nt = 0; nt < 2; nt++)
#pragma unroll
                    for (int h = 0; h < 2; h++) {
                        float* d = acc[mt][nt * 2 + h];
                        mma_bf16(d, ah[mt], bh[nt][h], bh[nt][h + 2]);
                        mma_bf16(d, ah[mt], bl[nt][h], bl[nt][h + 2]);
                        mma_bf16(d, al[mt], bh[nt][h], bh[nt][h + 2]);
                    }
        }
    }

    // epilogue
    const int g = lane >> 2, tig = lane & 3;
#pragma unroll
    for (int mt = 0; mt < 4; mt++) {
#pragma unroll
        for (int n8 = 0; n8 < 4; n8++) {
            const int col = n0 + wn * 32 + n8 * 8 + tig * 2;
            const float2 bv = *reinterpret_cast<const float2*>(bias + col);
            const int row = m0 + wm * 64 + mt * 16 + g;
            float* d = acc[mt][n8];
            float2 o0 = make_float2(d[0] + bv.x, d[1] + bv.y);
            float2 o1 = make_float2(d[2] + bv.x, d[3] + bv.y);
            if constexpr (SPLIT_OUT) {
                __nv_bfloat16 h0, h1, l0, l1;
                split1(o0.x, h0, l0); split1(o0.y, h1, l1);
                *reinterpret_cast<__nv_bfloat162*>(Ch + (size_t)row * N + col) =
                    __nv_bfloat162(h0, h1);
                *reinterpret_cast<__nv_bfloat162*>(Cl + (size_t)row * N + col) =
                    __nv_bfloat162(l0, l1);
                split1(o1.x, h0, l0); split1(o1.y, h1, l1);
                *reinterpret_cast<__nv_bfloat162*>(Ch + (size_t)(row + 8) * N + col) =
                    __nv_bfloat162(h0, h1);
                *reinterpret_cast<__nv_bfloat162*>(Cl + (size_t)(row + 8) * N + col) =
                    __nv_bfloat162(l0, l1);
            } else {
                *reinterpret_cast<float2*>(C + (size_t)row * N + col) = o0;
                *reinterpret_cast<float2*>(C + (size_t)(row + 8) * N + col) = o1;
            }
        }
    }
}

// ---------------- mma.sync flash attention (causal) ----------------
// Single barrier per k-tile (wait -> barrier -> issue next -> compute).
// Output written as bf16 hi/lo split (feeds proj GEMM directly).
#define AS 72
#define ATILE_B (64 * AS * 2)
#define A_STAGE0 (2 * ATILE_B)
#define A_STAGE_B (4 * ATILE_B)
#define ATTN_SMEM (A_STAGE0 + 2 * A_STAGE_B)  // 92160 B

__global__ __launch_bounds__(128) void attn_mma_kernel(
    const __nv_bfloat16* __restrict__ qkvh,
    const __nv_bfloat16* __restrict__ qkvl,
    __nv_bfloat16* __restrict__ yh, __nv_bfloat16* __restrict__ yl)
{
    extern __shared__ char smem[];
    const uint32_t sb = smem_u32(smem);
    const int tid = threadIdx.x;
    const int wid = tid >> 5, lane = tid & 31;
    const int g = lane >> 2, tig = lane & 3;

    const int bh = blockIdx.y;
    const int b = bh >> 4, h = bh & 15;
    const int qt = (int)gridDim.x - 1 - (int)blockIdx.x;  // longest first
    const int q0 = qt * 64;

    const size_t rowbase = (size_t)b * SEQ * QKV_N + h * HD;
    const uint32_t sQh = sb, sQl = sb + ATILE_B;

    auto issueKV = [&](int stage, int kt) {
        const int k0 = kt * 64;
        const uint32_t sbK = sb + A_STAGE0 + stage * A_STAGE_B;
#pragma unroll
        for (int i = 0; i < 4; i++) {
            const int cid = tid + 128 * i;
            const int r = cid >> 3, q = cid & 7;
            const size_t gK = rowbase + (size_t)(k0 + r) * QKV_N + D_MODEL + q * 8;
            const size_t gV = gK + D_MODEL;
            const uint32_t so = (r * AS + q * 8) * 2;
            cp16(sbK + so, qkvh + gK);
            cp16(sbK + ATILE_B + so, qkvl + gK);
            cp16(sbK + 2 * ATILE_B + so, qkvh + gV);
            cp16(sbK + 3 * ATILE_B + so, qkvl + gV);
        }
        CP_COMMIT();
    };

    // prologue: Q tile + KV stage 0 (one group)
    {
#pragma unroll
        for (int i = 0; i < 4; i++) {
            const int cid = tid + 128 * i;
            const int r = cid >> 3, q = cid & 7;
            const size_t go = rowbase + (size_t)(q0 + r) * QKV_N + q * 8;
            cp16(sQh + (r * AS + q * 8) * 2, qkvh + go);
            cp16(sQl + (r * AS + q * 8) * 2, qkvl + go);
        }
    }
    issueKV(0, 0);

    float m[2], l[2], oacc[8][4];
    m[0] = m[1] = -INFINITY;
    l[0] = l[1] = 0.f;
#pragma unroll
    for (int t = 0; t < 8; t++)
#pragma unroll
        for (int v = 0; v < 4; v++) oacc[t][v] = 0.f;

    uint32_t qh[4][4], ql[4][4];
    bool qloaded = false;
    const float scale = 0.125f;
    const int rowa = wid * 16 + (lane & 15);
    const int ko = (lane >> 4) * 8;

    for (int kt = 0; kt <= qt; kt++) {
        CP_WAIT0();          // stage kt resident
        __syncthreads();     // all warps done reading stage kt-1
        if (kt < qt) issueKV((kt + 1) & 1, kt + 1);  // overlaps compute

        const uint32_t sK = sb + A_STAGE0 + (kt & 1) * A_STAGE_B;
        const uint32_t sKh = sK, sKl = sK + ATILE_B;
        const uint32_t sVh = sK + 2 * ATILE_B, sVl = sK + 3 * ATILE_B;

        if (!qloaded) {
#pragma unroll
            for (int kc = 0; kc < 4; kc++) {
                ldsm_x4(qh[kc], sQh + (rowa * AS + kc * 16 + ko) * 2);
                ldsm_x4(ql[kc], sQl + (rowa * AS + kc * 16 + ko) * 2);
            }
            qloaded = true;
        }

        // S = Q K^T (3-term)
        float sacc[8][4];
#pragma unroll
        for (int t = 0; t < 8; t++)
#pragma unroll
            for (int v = 0; v < 4; v++) sacc[t][v] = 0.f;

#pragma unroll
        for (int kc = 0; kc < 4; kc++) {
#pragma unroll
            for (int nt = 0; nt < 4; nt++) {
                uint32_t kbh[4], kbl[4];
                const uint32_t ka = ((nt * 16 + (lane & 15)) * AS + kc * 16 + ko) * 2;
                ldsm_x4(kbh, sKh + ka);
                ldsm_x4(kbl, sKl + ka);
#pragma unroll
                for (int hh = 0; hh < 2; hh++) {
                    float* d = sacc[nt * 2 + hh];
                    mma_bf16(d, qh[kc], kbh[hh], kbh[hh + 2]);
                    mma_bf16(d, qh[kc], kbl[hh], kbl[hh + 2]);
                    mma_bf16(d, ql[kc], kbh[hh], kbh[hh + 2]);
                }
            }
        }

        // scale + causal mask
        const int k0 = kt * 64;
        if (kt == qt) {
#pragma unroll
            for (int t = 0; t < 8; t++)
#pragma unroll
                for (int v = 0; v < 4; v++) {
                    const int kg = k0 + t * 8 + 2 * tig + (v & 1);
                    const int qg = q0 + wid * 16 + g + (v >> 1) * 8;
                    sacc[t][v] = (kg <= qg) ? sacc[t][v] * scale : -INFINITY;
                }
        } else {
#pragma unroll
            for (int t = 0; t < 8; t++)
#pragma unroll
                for (int v = 0; v < 4; v++) sacc[t][v] *= scale;
        }

        // online softmax
#pragma unroll
        for (int rh = 0; rh < 2; rh++) {
            float mt = -INFINITY;
#pragma unroll
            for (int t = 0; t < 8; t++)
                mt = fmaxf(mt, fmaxf(sacc[t][rh * 2], sacc[t][rh * 2 + 1]));
            mt = fmaxf(mt, __shfl_xor_sync(0xffffffffu, mt, 1));
            mt = fmaxf(mt, __shfl_xor_sync(0xffffffffu, mt, 2));
            const float mn = fmaxf(m[rh], mt);
            const float corr = __expf(m[rh] - mn);
            m[rh] = mn;
            float ps = 0.f;
#pragma unroll
            for (int t = 0; t < 8; t++) {
                float p0 = __expf(sacc[t][rh * 2] - mn);
                float p1 = __expf(sacc[t][rh * 2 + 1] - mn);
                sacc[t][rh * 2] = p0;
                sacc[t][rh * 2 + 1] = p1;
                ps += p0 + p1;
            }
            ps += __shfl_xor_sync(0xffffffffu, ps, 1);
            ps += __shfl_xor_sync(0xffffffffu, ps, 2);
            l[rh] = l[rh] * corr + ps;
#pragma unroll
            for (int t = 0; t < 8; t++) {
                oacc[t][rh * 2] *= corr;
                oacc[t][rh * 2 + 1] *= corr;
            }
        }

        // P -> bf16 hi/lo fragments
        uint32_t ph[8][2], pl[8][2];
#pragma unroll
        for (int t = 0; t < 8; t++)
#pragma unroll
            for (int rh = 0; rh < 2; rh++) {
                float2 f = make_float2(sacc[t][rh * 2], sacc[t][rh * 2 + 1]);
                __nv_bfloat162 h2 = __floats2bfloat162_rn(f.x, f.y);
                float2 bk = __bfloat1622float2(h2);
                __nv_bfloat162 l2 = __floats2bfloat162_rn(f.x - bk.x, f.y - bk.y);
                ph[t][rh] = *reinterpret_cast<uint32_t*>(&h2);
                pl[t][rh] = *reinterpret_cast<uint32_t*>(&l2);
            }

        // O += P V (3-term)
        const int vrow = ((lane >> 4) & 1) * 8 + (lane & 7);
        const int vcol = ((lane >> 3) & 1) * 8;
#pragma unroll
        for (int jc = 0; jc < 4; jc++) {
            uint32_t pa_h[4] = {ph[2 * jc][0], ph[2 * jc][1],
                                ph[2 * jc + 1][0], ph[2 * jc + 1][1]};
            uint32_t pa_l[4] = {pl[2 * jc][0], pl[2 * jc][1],
                                pl[2 * jc + 1][0], pl[2 * jc + 1][1]};
#pragma unroll
            for (int dt = 0; dt < 4; dt++) {
                uint32_t vbh[4], vbl[4];
                const uint32_t va = ((jc * 16 + vrow) * AS + dt * 16 + vcol) * 2;
                ldsm_x4_t(vbh, sVh + va);
                ldsm_x4_t(vbl, sVl + va);
#pragma unroll
                for (int hh = 0; hh < 2; hh++) {
                    float* d = oacc[dt * 2 + hh];
                    mma_bf16(d, pa_h, vbh[hh], vbh[hh + 2]);
                    mma_bf16(d, pa_h, vbl[hh], vbl[hh + 2]);
                    mma_bf16(d, pa_l, vbh[hh], vbh[hh + 2]);
                }
            }
        }
    }

    // epilogue: write y split hi/lo
    const float inv0 = 1.f / l[0], inv1 = 1.f / l[1];
    const int row0 = q0 + wid * 16 + g;
#pragma unroll
    for (int t = 0; t < 8; t++) {
        const int col = h * HD + t * 8 + 2 * tig;
        const size_t o0i = ((size_t)b * SEQ + row0) * D_MODEL + col;
        const size_t o1i = ((size_t)b * SEQ + row0 + 8) * D_MODEL + col;
        __nv_bfloat16 h0, h1, l0, l1;
        split1(oacc[t][0] * inv0, h0, l0);
        split1(oacc[t][1] * inv0, h1, l1);
        *reinterpret_cast<__nv_bfloat162*>(yh + o0i) = __nv_bfloat162(h0, h1);
        *reinterpret_cast<__nv_bfloat162*>(yl + o0i) = __nv_bfloat162(l0, l1);
        split1(oacc[t][2] * inv1, h0, l0);
        split1(oacc[t][3] * inv1, h1, l1);
        *reinterpret_cast<__nv_bfloat162*>(yh + o1i) = __nv_bfloat162(h0, h1);
        *reinterpret_cast<__nv_bfloat162*>(yl + o1i) = __nv_bfloat162(l0, l1);
    }
}

// ---------------------------------------------------------------------------
extern "C" void kernel_launch(void* const* d_in, const int* in_sizes, int n_in,
                              void* d_out, int out_size)
{
    const float* x      = (const float*)d_in[0];
    const float* W_attn = (const float*)d_in[1];
    const float* b_attn = (const float*)d_in[2];
    const float* W_proj = (const float*)d_in[3];
    const float* b_proj = (const float*)d_in[4];
    float* out = (float*)d_out;

    __nv_bfloat16 *xh, *xl, *yh, *yl, *qvh, *qvl, *wah, *wal, *wph, *wpl;
    cudaGetSymbolAddress((void**)&xh, g_x_hi);
    cudaGetSymbolAddress((void**)&xl, g_x_lo);
    cudaGetSymbolAddress((void**)&yh, g_y_hi);
    cudaGetSymbolAddress((void**)&yl, g_y_lo);
    cudaGetSymbolAddress((void**)&qvh, g_qkv_hi);
    cudaGetSymbolAddress((void**)&qvl, g_qkv_lo);
    cudaGetSymbolAddress((void**)&wah, g_wat_hi);
    cudaGetSymbolAddress((void**)&wal, g_wat_lo);
    cudaGetSymbolAddress((void**)&wph, g_wpt_hi);
    cudaGetSymbolAddress((void**)&wpl, g_wpt_lo);

    cudaFuncSetAttribute(gemm_mma_kernel<true>,
                         cudaFuncAttributeMaxDynamicSharedMemorySize, GEMM_SMEM);
    cudaFuncSetAttribute(gemm_mma_kernel<false>,
                         cudaFuncAttributeMaxDynamicSharedMemorySize, GEMM_SMEM);
    cudaFuncSetAttribute(attn_mma_kernel,
                         cudaFuncAttributeMaxDynamicSharedMemorySize, ATTN_SMEM);

    const int NX = M_TOTAL * KDIM;

    // prep
    split_kernel<<<NX / (256 * 4), 256>>>(x, xh, xl, NX);
    transpose_split_kernel<<<dim3(QKV_N / 32, KDIM / 32), dim3(32, 8)>>>(
        W_attn, wah, wal, KDIM, QKV_N);
    transpose_split_kernel<<<dim3(D_MODEL / 32, KDIM / 32), dim3(32, 8)>>>(
        W_proj, wph, wpl, KDIM, D_MODEL);

    // 1) qkv = x @ W_attn + b_attn  -> split bf16 hi/lo directly
    gemm_mma_kernel<true><<<dim3(QKV_N / 128, M_TOTAL / 128), 256, GEMM_SMEM>>>(
        xh, xl, wah, wal, b_attn, nullptr, qvh, qvl, QKV_N);

    // 2) flash attention (mma.sync) -> y split hi/lo
    attn_mma_kernel<<<dim3(SEQ / 64, BATCH * N_HEADS), 128, ATTN_SMEM>>>(
        qvh, qvl, yh, yl);

    // 3) out = y @ W_proj + b_proj  (fp32 out)
    gemm_mma_kernel<false><<<dim3(D_MODEL / 128, M_TOTAL / 128), 256, GEMM_SMEM>>>(
        yh, yl, wph, wpl, b_proj, out, nullptr, nullptr, D_MODEL);
}

// round 9
// speedup vs baseline: 1.7647x; 1.0641x over previous
#include <cuda_runtime.h>
#include <cuda_bf16.h>
#include <math.h>
#include <stdint.h>

#define D_MODEL 1024
#define N_HEADS 16
#define HD 64
#define BATCH 2
#define SEQ 2048
#define M_TOTAL (BATCH * SEQ)   // 4096
#define QKV_N (3 * D_MODEL)     // 3072
#define KDIM 1024

// ---------------- scratch (device globals; allocation-free) ----------------
__device__ __align__(256) __nv_bfloat16 g_x_hi[(size_t)M_TOTAL * KDIM];
__device__ __align__(256) __nv_bfloat16 g_x_lo[(size_t)M_TOTAL * KDIM];
__device__ __align__(256) __nv_bfloat16 g_y_hi[(size_t)M_TOTAL * KDIM];
__device__ __align__(256) __nv_bfloat16 g_y_lo[(size_t)M_TOTAL * KDIM];
__device__ __align__(256) __nv_bfloat16 g_qkv_hi[(size_t)M_TOTAL * QKV_N];
__device__ __align__(256) __nv_bfloat16 g_qkv_lo[(size_t)M_TOTAL * QKV_N];
__device__ __align__(256) __nv_bfloat16 g_wat_hi[(size_t)QKV_N * KDIM];
__device__ __align__(256) __nv_bfloat16 g_wat_lo[(size_t)QKV_N * KDIM];
__device__ __align__(256) __nv_bfloat16 g_wpt_hi[(size_t)D_MODEL * KDIM];
__device__ __align__(256) __nv_bfloat16 g_wpt_lo[(size_t)D_MODEL * KDIM];

// ---------------- helpers ----------------
__device__ __forceinline__ uint32_t smem_u32(const void* p) {
    uint32_t a;
    asm("{ .reg .u64 t; cvta.to.shared.u64 t, %1; cvt.u32.u64 %0, t; }"
        : "=r"(a) : "l"(p));
    return a;
}

__device__ __forceinline__ void cp16(uint32_t dst, const void* src) {
    asm volatile("cp.async.cg.shared.global [%0], [%1], 16;" :: "r"(dst), "l"(src));
}
#define CP_COMMIT() asm volatile("cp.async.commit_group;" ::: "memory")
#define CP_WAIT0()  asm volatile("cp.async.wait_group 0;" ::: "memory")

__device__ __forceinline__ void ldsm_x4(uint32_t* r, uint32_t addr) {
    asm volatile("ldmatrix.sync.aligned.m8n8.x4.shared.b16 {%0,%1,%2,%3}, [%4];"
        : "=r"(r[0]), "=r"(r[1]), "=r"(r[2]), "=r"(r[3]) : "r"(addr));
}
__device__ __forceinline__ void ldsm_x4_t(uint32_t* r, uint32_t addr) {
    asm volatile("ldmatrix.sync.aligned.m8n8.x4.trans.shared.b16 {%0,%1,%2,%3}, [%4];"
        : "=r"(r[0]), "=r"(r[1]), "=r"(r[2]), "=r"(r[3]) : "r"(addr));
}

__device__ __forceinline__ void mma_bf16(float* d, const uint32_t* a,
                                         uint32_t b0, uint32_t b1) {
    asm volatile(
        "mma.sync.aligned.m16n8k16.row.col.f32.bf16.bf16.f32 "
        "{%0,%1,%2,%3}, {%4,%5,%6,%7}, {%8,%9}, {%0,%1,%2,%3};"
        : "+f"(d[0]), "+f"(d[1]), "+f"(d[2]), "+f"(d[3])
        : "r"(a[0]), "r"(a[1]), "r"(a[2]), "r"(a[3]), "r"(b0), "r"(b1));
}

// ---------------- conversion kernels ----------------
__device__ __forceinline__ void split1(float v, __nv_bfloat16& h, __nv_bfloat16& l) {
    h = __float2bfloat16(v);
    l = __float2bfloat16(v - __bfloat162float(h));
}

__global__ void split_kernel(const float* __restrict__ in,
                             __nv_bfloat16* __restrict__ hi,
                             __nv_bfloat16* __restrict__ lo, int n)
{
    int idx = (blockIdx.x * blockDim.x + threadIdx.x) * 4;
    if (idx >= n) return;
    float4 v = *reinterpret_cast<const float4*>(in + idx);
    __nv_bfloat16 h0, h1, h2, h3, l0, l1, l2, l3;
    split1(v.x, h0, l0); split1(v.y, h1, l1);
    split1(v.z, h2, l2); split1(v.w, h3, l3);
    *reinterpret_cast<__nv_bfloat162*>(hi + idx)     = __nv_bfloat162(h0, h1);
    *reinterpret_cast<__nv_bfloat162*>(hi + idx + 2) = __nv_bfloat162(h2, h3);
    *reinterpret_cast<__nv_bfloat162*>(lo + idx)     = __nv_bfloat162(l0, l1);
    *reinterpret_cast<__nv_bfloat162*>(lo + idx + 2) = __nv_bfloat162(l2, l3);
}

__global__ void transpose_split_kernel(const float* __restrict__ W,
                                       __nv_bfloat16* __restrict__ th,
                                       __nv_bfloat16* __restrict__ tl,
                                       int K, int N)
{
    __shared__ float t[32][33];
    const int tx = threadIdx.x, ty = threadIdx.y;
    const int n0 = blockIdx.x * 32, k0 = blockIdx.y * 32;
#pragma unroll
    for (int j = ty; j < 32; j += 8)
        t[j][tx] = W[(size_t)(k0 + j) * N + n0 + tx];
    __syncthreads();
#pragma unroll
    for (int j = ty; j < 32; j += 8) {
        float v = t[tx][j];
        __nv_bfloat16 h, l;
        split1(v, h, l);
        size_t o = (size_t)(n0 + j) * K + k0 + tx;
        th[o] = h;
        tl[o] = l;
    }
}

// ---------------- mma.sync bf16 3-term GEMM ----------------
// Term-major MMA ordering: 16 independent accumulators between revisits
// of the same acc -> HMMA latency fully hidden by rt-limited streaming.
#define TS 40
#define TILE_B (128 * TS * 2)
#define STAGE_B (4 * TILE_B)
#define GEMM_SMEM (2 * STAGE_B)

template <bool SPLIT_OUT>
__global__ __launch_bounds__(256) void gemm_mma_kernel(
    const __nv_bfloat16* __restrict__ Ah, const __nv_bfloat16* __restrict__ Al,
    const __nv_bfloat16* __restrict__ Bh, const __nv_bfloat16* __restrict__ Bl,
    const float* __restrict__ bias, float* __restrict__ C,
    __nv_bfloat16* __restrict__ Ch, __nv_bfloat16* __restrict__ Cl, int N)
{
    extern __shared__ char smem[];
    const uint32_t sbase = smem_u32(smem);
    const int tid = threadIdx.x;
    const int wid = tid >> 5, lane = tid & 31;
    const int m0 = blockIdx.y * 128, n0 = blockIdx.x * 128;
    const int wm = wid >> 2, wn = wid & 3;

    const __nv_bfloat16* aB[2] = {Ah + (size_t)m0 * KDIM, Al + (size_t)m0 * KDIM};
    const __nv_bfloat16* bB[2] = {Bh + (size_t)n0 * KDIM, Bl + (size_t)n0 * KDIM};

    float acc[4][4][4];
#pragma unroll
    for (int i = 0; i < 4; i++)
#pragma unroll
        for (int j = 0; j < 4; j++)
#pragma unroll
            for (int v = 0; v < 4; v++) acc[i][j][v] = 0.f;

    const int NC = KDIM / 32;

    auto issue = [&](int stage, int c) {
        const int k0 = c * 32;
        const uint32_t sb = sbase + stage * STAGE_B;
#pragma unroll
        for (int t = 0; t < 2; t++) {
#pragma unroll
            for (int i = 0; i < 2; i++) {
                const int cid = tid + 256 * i;
                const int r = cid >> 2, q = cid & 3;
                cp16(sb + t * TILE_B + (r * TS + q * 8) * 2,
                     aB[t] + (size_t)r * KDIM + k0 + q * 8);
                cp16(sb + (2 + t) * TILE_B + (r * TS + q * 8) * 2,
                     bB[t] + (size_t)r * KDIM + k0 + q * 8);
            }
        }
        CP_COMMIT();
    };

    issue(0, 0);

    for (int c = 0; c < NC; c++) {
        CP_WAIT0();
        __syncthreads();
        if (c + 1 < NC) issue((c + 1) & 1, c + 1);

        const int st = c & 1;
        const uint32_t sAh = sbase + st * STAGE_B;
        const uint32_t sAl = sAh + TILE_B;
        const uint32_t sBh = sAh + 2 * TILE_B;
        const uint32_t sBl = sAh + 3 * TILE_B;

        const int rowa = wm * 64 + (lane & 15);
        const int rowb = wn * 32 + (lane & 15);
        const int ko = (lane >> 4) * 8;

#pragma unroll
        for (int kt = 0; kt < 2; kt++) {
            const int k = kt * 16 + ko;
            uint32_t ah[4][4], al[4][4], bh[2][4], bl[2][4];
#pragma unroll
            for (int mt = 0; mt < 4; mt++) {
                ldsm_x4(ah[mt], sAh + ((rowa + mt * 16) * TS + k) * 2);
                ldsm_x4(al[mt], sAl + ((rowa + mt * 16) * TS + k) * 2);
            }
#pragma unroll
            for (int nt = 0; nt < 2; nt++) {
                ldsm_x4(bh[nt], sBh + ((rowb + nt * 16) * TS + k) * 2);
                ldsm_x4(bl[nt], sBl + ((rowb + nt * 16) * TS + k) * 2);
            }
            // term-major: all Ah*Bh, then all Ah*Bl, then all Al*Bh
#pragma unroll
            for (int mt = 0; mt < 4; mt++)
#pragma unroll
                for (int nt = 0; nt < 2; nt++)
#pragma unroll
                    for (int h = 0; h < 2; h++)
                        mma_bf16(acc[mt][nt * 2 + h], ah[mt],
                                 bh[nt][h], bh[nt][h + 2]);
#pragma unroll
            for (int mt = 0; mt < 4; mt++)
#pragma unroll
                for (int nt = 0; nt < 2; nt++)
#pragma unroll
                    for (int h = 0; h < 2; h++)
                        mma_bf16(acc[mt][nt * 2 + h], ah[mt],
                                 bl[nt][h], bl[nt][h + 2]);
#pragma unroll
            for (int mt = 0; mt < 4; mt++)
#pragma unroll
                for (int nt = 0; nt < 2; nt++)
#pragma unroll
                    for (int h = 0; h < 2; h++)
                        mma_bf16(acc[mt][nt * 2 + h], al[mt],
                                 bh[nt][h], bh[nt][h + 2]);
        }
    }

    // epilogue
    const int g = lane >> 2, tig = lane & 3;
#pragma unroll
    for (int mt = 0; mt < 4; mt++) {
#pragma unroll
        for (int n8 = 0; n8 < 4; n8++) {
            const int col = n0 + wn * 32 + n8 * 8 + tig * 2;
            const float2 bv = *reinterpret_cast<const float2*>(bias + col);
            const int row = m0 + wm * 64 + mt * 16 + g;
            float* d = acc[mt][n8];
            float2 o0 = make_float2(d[0] + bv.x, d[1] + bv.y);
            float2 o1 = make_float2(d[2] + bv.x, d[3] + bv.y);
            if constexpr (SPLIT_OUT) {
                __nv_bfloat16 h0, h1, l0, l1;
                split1(o0.x, h0, l0); split1(o0.y, h1, l1);
                *reinterpret_cast<__nv_bfloat162*>(Ch + (size_t)row * N + col) =
                    __nv_bfloat162(h0, h1);
                *reinterpret_cast<__nv_bfloat162*>(Cl + (size_t)row * N + col) =
                    __nv_bfloat162(l0, l1);
                split1(o1.x, h0, l0); split1(o1.y, h1, l1);
                *reinterpret_cast<__nv_bfloat162*>(Ch + (size_t)(row + 8) * N + col) =
                    __nv_bfloat162(h0, h1);
                *reinterpret_cast<__nv_bfloat162*>(Cl + (size_t)(row + 8) * N + col) =
                    __nv_bfloat162(l0, l1);
            } else {
                *reinterpret_cast<float2*>(C + (size_t)row * N + col) = o0;
                *reinterpret_cast<float2*>(C + (size_t)(row + 8) * N + col) = o1;
            }
        }
    }
}

// ---------------- mma.sync flash attention (causal) ----------------
// Term-major MMA ordering in both S and PV loops (8 rotating accumulators).
#define AS 72
#define ATILE_B (64 * AS * 2)
#define A_STAGE0 (2 * ATILE_B)
#define A_STAGE_B (4 * ATILE_B)
#define ATTN_SMEM (A_STAGE0 + 2 * A_STAGE_B)  // 92160 B

__global__ __launch_bounds__(128) void attn_mma_kernel(
    const __nv_bfloat16* __restrict__ qkvh,
    const __nv_bfloat16* __restrict__ qkvl,
    __nv_bfloat16* __restrict__ yh, __nv_bfloat16* __restrict__ yl)
{
    extern __shared__ char smem[];
    const uint32_t sb = smem_u32(smem);
    const int tid = threadIdx.x;
    const int wid = tid >> 5, lane = tid & 31;
    const int g = lane >> 2, tig = lane & 3;

    const int bh = blockIdx.y;
    const int b = bh >> 4, h = bh & 15;
    const int qt = (int)gridDim.x - 1 - (int)blockIdx.x;
    const int q0 = qt * 64;

    const size_t rowbase = (size_t)b * SEQ * QKV_N + h * HD;
    const uint32_t sQh = sb, sQl = sb + ATILE_B;

    auto issueKV = [&](int stage, int kt) {
        const int k0 = kt * 64;
        const uint32_t sbK = sb + A_STAGE0 + stage * A_STAGE_B;
#pragma unroll
        for (int i = 0; i < 4; i++) {
            const int cid = tid + 128 * i;
            const int r = cid >> 3, q = cid & 7;
            const size_t gK = rowbase + (size_t)(k0 + r) * QKV_N + D_MODEL + q * 8;
            const size_t gV = gK + D_MODEL;
            const uint32_t so = (r * AS + q * 8) * 2;
            cp16(sbK + so, qkvh + gK);
            cp16(sbK + ATILE_B + so, qkvl + gK);
            cp16(sbK + 2 * ATILE_B + so, qkvh + gV);
            cp16(sbK + 3 * ATILE_B + so, qkvl + gV);
        }
        CP_COMMIT();
    };

    {
#pragma unroll
        for (int i = 0; i < 4; i++) {
            const int cid = tid + 128 * i;
            const int r = cid >> 3, q = cid & 7;
            const size_t go = rowbase + (size_t)(q0 + r) * QKV_N + q * 8;
            cp16(sQh + (r * AS + q * 8) * 2, qkvh + go);
            cp16(sQl + (r * AS + q * 8) * 2, qkvl + go);
        }
    }
    issueKV(0, 0);

    float m[2], l[2], oacc[8][4];
    m[0] = m[1] = -INFINITY;
    l[0] = l[1] = 0.f;
#pragma unroll
    for (int t = 0; t < 8; t++)
#pragma unroll
        for (int v = 0; v < 4; v++) oacc[t][v] = 0.f;

    uint32_t qh[4][4], ql[4][4];
    bool qloaded = false;
    const float scale = 0.125f;
    const int rowa = wid * 16 + (lane & 15);
    const int ko = (lane >> 4) * 8;

    for (int kt = 0; kt <= qt; kt++) {
        CP_WAIT0();
        __syncthreads();
        if (kt < qt) issueKV((kt + 1) & 1, kt + 1);

        const uint32_t sK = sb + A_STAGE0 + (kt & 1) * A_STAGE_B;
        const uint32_t sKh = sK, sKl = sK + ATILE_B;
        const uint32_t sVh = sK + 2 * ATILE_B, sVl = sK + 3 * ATILE_B;

        if (!qloaded) {
#pragma unroll
            for (int kc = 0; kc < 4; kc++) {
                ldsm_x4(qh[kc], sQh + (rowa * AS + kc * 16 + ko) * 2);
                ldsm_x4(ql[kc], sQl + (rowa * AS + kc * 16 + ko) * 2);
            }
            qloaded = true;
        }

        // ---- S = Q K^T (3-term, term-major per kc slice) ----
        float sacc[8][4];
#pragma unroll
        for (int t = 0; t < 8; t++)
#pragma unroll
            for (int v = 0; v < 4; v++) sacc[t][v] = 0.f;

#pragma unroll
        for (int kc = 0; kc < 4; kc++) {
            uint32_t kbh[4][4], kbl[4][4];
#pragma unroll
            for (int nt = 0; nt < 4; nt++) {
                const uint32_t ka = ((nt * 16 + (lane & 15)) * AS + kc * 16 + ko) * 2;
                ldsm_x4(kbh[nt], sKh + ka);
                ldsm_x4(kbl[nt], sKl + ka);
            }
#pragma unroll
            for (int nt = 0; nt < 4; nt++)
#pragma unroll
                for (int hh = 0; hh < 2; hh++)
                    mma_bf16(sacc[nt * 2 + hh], qh[kc],
                             kbh[nt][hh], kbh[nt][hh + 2]);
#pragma unroll
            for (int nt = 0; nt < 4; nt++)
#pragma unroll
                for (int hh = 0; hh < 2; hh++)
                    mma_bf16(sacc[nt * 2 + hh], qh[kc],
                             kbl[nt][hh], kbl[nt][hh + 2]);
#pragma unroll
            for (int nt = 0; nt < 4; nt++)
#pragma unroll
                for (int hh = 0; hh < 2; hh++)
                    mma_bf16(sacc[nt * 2 + hh], ql[kc],
                             kbh[nt][hh], kbh[nt][hh + 2]);
        }

        // scale + causal mask
        const int k0 = kt * 64;
        if (kt == qt) {
#pragma unroll
            for (int t = 0; t < 8; t++)
#pragma unroll
                for (int v = 0; v < 4; v++) {
                    const int kg = k0 + t * 8 + 2 * tig + (v & 1);
                    const int qg = q0 + wid * 16 + g + (v >> 1) * 8;
                    sacc[t][v] = (kg <= qg) ? sacc[t][v] * scale : -INFINITY;
                }
        } else {
#pragma unroll
            for (int t = 0; t < 8; t++)
#pragma unroll
                for (int v = 0; v < 4; v++) sacc[t][v] *= scale;
        }

        // online softmax
#pragma unroll
        for (int rh = 0; rh < 2; rh++) {
            float mt = -INFINITY;
#pragma unroll
            for (int t = 0; t < 8; t++)
                mt = fmaxf(mt, fmaxf(sacc[t][rh * 2], sacc[t][rh * 2 + 1]));
            mt = fmaxf(mt, __shfl_xor_sync(0xffffffffu, mt, 1));
            mt = fmaxf(mt, __shfl_xor_sync(0xffffffffu, mt, 2));
            const float mn = fmaxf(m[rh], mt);
            const float corr = __expf(m[rh] - mn);
            m[rh] = mn;
            float ps = 0.f;
#pragma unroll
            for (int t = 0; t < 8; t++) {
                float p0 = __expf(sacc[t][rh * 2] - mn);
                float p1 = __expf(sacc[t][rh * 2 + 1] - mn);
                sacc[t][rh * 2] = p0;
                sacc[t][rh * 2 + 1] = p1;
                ps += p0 + p1;
            }
            ps += __shfl_xor_sync(0xffffffffu, ps, 1);
            ps += __shfl_xor_sync(0xffffffffu, ps, 2);
            l[rh] = l[rh] * corr + ps;
#pragma unroll
            for (int t = 0; t < 8; t++) {
                oacc[t][rh * 2] *= corr;
                oacc[t][rh * 2 + 1] *= corr;
            }
        }

        // P -> bf16 hi/lo fragments
        uint32_t ph[8][2], pl[8][2];
#pragma unroll
        for (int t = 0; t < 8; t++)
#pragma unroll
            for (int rh = 0; rh < 2; rh++) {
                float2 f = make_float2(sacc[t][rh * 2], sacc[t][rh * 2 + 1]);
                __nv_bfloat162 h2 = __floats2bfloat162_rn(f.x, f.y);
                float2 bk = __bfloat1622float2(h2);
                __nv_bfloat162 l2 = __floats2bfloat162_rn(f.x - bk.x, f.y - bk.y);
                ph[t][rh] = *reinterpret_cast<uint32_t*>(&h2);
                pl[t][rh] = *reinterpret_cast<uint32_t*>(&l2);
            }

        // ---- O += P V (3-term, term-major per jc slice) ----
        const int vrow = ((lane >> 4) & 1) * 8 + (lane & 7);
        const int vcol = ((lane >> 3) & 1) * 8;
#pragma unroll
        for (int jc = 0; jc < 4; jc++) {
            uint32_t pa_h[4] = {ph[2 * jc][0], ph[2 * jc][1],
                                ph[2 * jc + 1][0], ph[2 * jc + 1][1]};
            uint32_t pa_l[4] = {pl[2 * jc][0], pl[2 * jc][1],
                                pl[2 * jc + 1][0], pl[2 * jc + 1][1]};
            uint32_t vbh[4][4], vbl[4][4];
#pragma unroll
            for (int dt = 0; dt < 4; dt++) {
                const uint32_t va = ((jc * 16 + vrow) * AS + dt * 16 + vcol) * 2;
                ldsm_x4_t(vbh[dt], sVh + va);
                ldsm_x4_t(vbl[dt], sVl + va);
            }
#pragma unroll
            for (int dt = 0; dt < 4; dt++)
#pragma unroll
                for (int hh = 0; hh < 2; hh++)
                    mma_bf16(oacc[dt * 2 + hh], pa_h,
                             vbh[dt][hh], vbh[dt][hh + 2]);
#pragma unroll
            for (int dt = 0; dt < 4; dt++)
#pragma unroll
                for (int hh = 0; hh < 2; hh++)
                    mma_bf16(oacc[dt * 2 + hh], pa_h,
                             vbl[dt][hh], vbl[dt][hh + 2]);
#pragma unroll
            for (int dt = 0; dt < 4; dt++)
#pragma unroll
                for (int hh = 0; hh < 2; hh++)
                    mma_bf16(oacc[dt * 2 + hh], pa_l,
                             vbh[dt][hh], vbh[dt][hh + 2]);
        }
    }

    // epilogue: write y split hi/lo
    const float inv0 = 1.f / l[0], inv1 = 1.f / l[1];
    const int row0 = q0 + wid * 16 + g;
#pragma unroll
    for (int t = 0; t < 8; t++) {
        const int col = h * HD + t * 8 + 2 * tig;
        const size_t o0i = ((size_t)b * SEQ + row0) * D_MODEL + col;
        const size_t o1i = ((size_t)b * SEQ + row0 + 8) * D_MODEL + col;
        __nv_bfloat16 h0, h1, l0, l1;
        split1(oacc[t][0] * inv0, h0, l0);
        split1(oacc[t][1] * inv0, h1, l1);
        *reinterpret_cast<__nv_bfloat162*>(yh + o0i) = __nv_bfloat162(h0, h1);
        *reinterpret_cast<__nv_bfloat162*>(yl + o0i) = __nv_bfloat162(l0, l1);
        split1(oacc[t][2] * inv1, h0, l0);
        split1(oacc[t][3] * inv1, h1, l1);
        *reinterpret_cast<__nv_bfloat162*>(yh + o1i) = __nv_bfloat162(h0, h1);
        *reinterpret_cast<__nv_bfloat162*>(yl + o1i) = __nv_bfloat162(l0, l1);
    }
}

// ---------------------------------------------------------------------------
extern "C" void kernel_launch(void* const* d_in, const int* in_sizes, int n_in,
                              void* d_out, int out_size)
{
    const float* x      = (const float*)d_in[0];
    const float* W_attn = (const float*)d_in[1];
    const float* b_attn = (const float*)d_in[2];
    const float* W_proj = (const float*)d_in[3];
    const float* b_proj = (const float*)d_in[4];
    float* out = (float*)d_out;

    __nv_bfloat16 *xh, *xl, *yh, *yl, *qvh, *qvl, *wah, *wal, *wph, *wpl;
    cudaGetSymbolAddress((void**)&xh, g_x_hi);
    cudaGetSymbolAddress((void**)&xl, g_x_lo);
    cudaGetSymbolAddress((void**)&yh, g_y_hi);
    cudaGetSymbolAddress((void**)&yl, g_y_lo);
    cudaGetSymbolAddress((void**)&qvh, g_qkv_hi);
    cudaGetSymbolAddress((void**)&qvl, g_qkv_lo);
    cudaGetSymbolAddress((void**)&wah, g_wat_hi);
    cudaGetSymbolAddress((void**)&wal, g_wat_lo);
    cudaGetSymbolAddress((void**)&wph, g_wpt_hi);
    cudaGetSymbolAddress((void**)&wpl, g_wpt_lo);

    cudaFuncSetAttribute(gemm_mma_kernel<true>,
                         cudaFuncAttributeMaxDynamicSharedMemorySize, GEMM_SMEM);
    cudaFuncSetAttribute(gemm_mma_kernel<false>,
                         cudaFuncAttributeMaxDynamicSharedMemorySize, GEMM_SMEM);
    cudaFuncSetAttribute(attn_mma_kernel,
                         cudaFuncAttributeMaxDynamicSharedMemorySize, ATTN_SMEM);

    const int NX = M_TOTAL * KDIM;

    split_kernel<<<NX / (256 * 4), 256>>>(x, xh, xl, NX);
    transpose_split_kernel<<<dim3(QKV_N / 32, KDIM / 32), dim3(32, 8)>>>(
        W_attn, wah, wal, KDIM, QKV_N);
    transpose_split_kernel<<<dim3(D_MODEL / 32, KDIM / 32), dim3(32, 8)>>>(
        W_proj, wph, wpl, KDIM, D_MODEL);

    gemm_mma_kernel<true><<<dim3(QKV_N / 128, M_TOTAL / 128), 256, GEMM_SMEM>>>(
        xh, xl, wah, wal, b_attn, nullptr, qvh, qvl, QKV_N);

    attn_mma_kernel<<<dim3(SEQ / 64, BATCH * N_HEADS), 128, ATTN_SMEM>>>(
        qvh, qvl, yh, yl);

    gemm_mma_kernel<false><<<dim3(D_MODEL / 128, M_TOTAL / 128), 256, GEMM_SMEM>>>(
        yh, yl, wph, wpl, b_proj, out, nullptr, nullptr, D_MODEL);
}

// round 11
// speedup vs baseline: 2.1402x; 1.2128x over previous
#include <cuda_runtime.h>
#include <cuda_bf16.h>
#include <cuda_fp16.h>
#include <math.h>
#include <stdint.h>

#define D_MODEL 1024
#define N_HEADS 16
#define HD 64
#define BATCH 2
#define SEQ 2048
#define M_TOTAL (BATCH * SEQ)   // 4096
#define QKV_N (3 * D_MODEL)     // 3072
#define KDIM 1024

// ---------------- scratch (device globals; allocation-free) ----------------
__device__ __align__(256) __half g_x_hi[(size_t)M_TOTAL * KDIM];
__device__ __align__(256) __half g_x_lo[(size_t)M_TOTAL * KDIM];
__device__ __align__(256) __half g_y_hi[(size_t)M_TOTAL * KDIM];
__device__ __align__(256) __half g_y_lo[(size_t)M_TOTAL * KDIM];
__device__ __align__(256) __nv_bfloat16 g_qkv_hi[(size_t)M_TOTAL * QKV_N];
__device__ __align__(256) __nv_bfloat16 g_qkv_lo[(size_t)M_TOTAL * QKV_N];
__device__ __align__(256) __half g_wat[(size_t)QKV_N * KDIM];   // W_attn^T fp16
__device__ __align__(256) __half g_wpt[(size_t)D_MODEL * KDIM]; // W_proj^T fp16

// ---------------- helpers ----------------
__device__ __forceinline__ uint32_t smem_u32(const void* p) {
    uint32_t a;
    asm("{ .reg .u64 t; cvta.to.shared.u64 t, %1; cvt.u32.u64 %0, t; }"
        : "=r"(a) : "l"(p));
    return a;
}

__device__ __forceinline__ void cp16(uint32_t dst, const void* src) {
    asm volatile("cp.async.cg.shared.global [%0], [%1], 16;" :: "r"(dst), "l"(src));
}
#define CP_COMMIT() asm volatile("cp.async.commit_group;" ::: "memory")
#define CP_WAIT0()  asm volatile("cp.async.wait_group 0;" ::: "memory")

__device__ __forceinline__ void ldsm_x4(uint32_t* r, uint32_t addr) {
    asm volatile("ldmatrix.sync.aligned.m8n8.x4.shared.b16 {%0,%1,%2,%3}, [%4];"
        : "=r"(r[0]), "=r"(r[1]), "=r"(r[2]), "=r"(r[3]) : "r"(addr));
}
__device__ __forceinline__ void ldsm_x4_t(uint32_t* r, uint32_t addr) {
    asm volatile("ldmatrix.sync.aligned.m8n8.x4.trans.shared.b16 {%0,%1,%2,%3}, [%4];"
        : "=r"(r[0]), "=r"(r[1]), "=r"(r[2]), "=r"(r[3]) : "r"(addr));
}

__device__ __forceinline__ void mma_bf16(float* d, const uint32_t* a,
                                         uint32_t b0, uint32_t b1) {
    asm volatile(
        "mma.sync.aligned.m16n8k16.row.col.f32.bf16.bf16.f32 "
        "{%0,%1,%2,%3}, {%4,%5,%6,%7}, {%8,%9}, {%0,%1,%2,%3};"
        : "+f"(d[0]), "+f"(d[1]), "+f"(d[2]), "+f"(d[3])
        : "r"(a[0]), "r"(a[1]), "r"(a[2]), "r"(a[3]), "r"(b0), "r"(b1));
}

__device__ __forceinline__ void mma_fp16(float* d, const uint32_t* a,
                                         uint32_t b0, uint32_t b1) {
    asm volatile(
        "mma.sync.aligned.m16n8k16.row.col.f32.f16.f16.f32 "
        "{%0,%1,%2,%3}, {%4,%5,%6,%7}, {%8,%9}, {%0,%1,%2,%3};"
        : "+f"(d[0]), "+f"(d[1]), "+f"(d[2]), "+f"(d[3])
        : "r"(a[0]), "r"(a[1]), "r"(a[2]), "r"(a[3]), "r"(b0), "r"(b1));
}

// ---------------- conversion kernels ----------------
__device__ __forceinline__ void split1(float v, __nv_bfloat16& h, __nv_bfloat16& l) {
    h = __float2bfloat16(v);
    l = __float2bfloat16(v - __bfloat162float(h));
}
__device__ __forceinline__ void split1h(float v, __half& h, __half& l) {
    h = __float2half_rn(v);
    l = __float2half_rn(v - __half2float(h));
}

// float -> fp16 hi/lo
__global__ void split_half_kernel(const float* __restrict__ in,
                                  __half* __restrict__ hi,
                                  __half* __restrict__ lo, int n)
{
    int idx = (blockIdx.x * blockDim.x + threadIdx.x) * 4;
    if (idx >= n) return;
    float4 v = *reinterpret_cast<const float4*>(in + idx);
    __half h0, h1, h2, h3, l0, l1, l2, l3;
    split1h(v.x, h0, l0); split1h(v.y, h1, l1);
    split1h(v.z, h2, l2); split1h(v.w, h3, l3);
    *reinterpret_cast<__half2*>(hi + idx)     = __half2(h0, h1);
    *reinterpret_cast<__half2*>(hi + idx + 2) = __half2(h2, h3);
    *reinterpret_cast<__half2*>(lo + idx)     = __half2(l0, l1);
    *reinterpret_cast<__half2*>(lo + idx + 2) = __half2(l2, l3);
}

// W [K,N] -> Wt [N,K] fp16 single
__global__ void transpose_half_kernel(const float* __restrict__ W,
                                      __half* __restrict__ t16, int K, int N)
{
    __shared__ float t[32][33];
    const int tx = threadIdx.x, ty = threadIdx.y;
    const int n0 = blockIdx.x * 32, k0 = blockIdx.y * 32;
#pragma unroll
    for (int j = ty; j < 32; j += 8)
        t[j][tx] = W[(size_t)(k0 + j) * N + n0 + tx];
    __syncthreads();
#pragma unroll
    for (int j = ty; j < 32; j += 8)
        t16[(size_t)(n0 + j) * K + k0 + tx] = __float2half_rn(t[tx][j]);
}

// ---------------- mma.sync fp16 2-term GEMM ----------------
// C[M,N] = (Ah + Al)[M,K] @ B[N,K]^T + bias, fp32 acc.
// A fp16 hi+lo (22-bit exact); B fp16 single. 3 streams, 2 MMA terms.
#define TS 40
#define TILE_B (128 * TS * 2)          // 10240 B
#define STAGE_B (3 * TILE_B)           // Ah, Al, B
#define GEMM_SMEM (2 * STAGE_B)        // 61440 B

template <bool SPLIT_OUT>
__global__ __launch_bounds__(256) void gemm_mma_kernel(
    const __half* __restrict__ Ah, const __half* __restrict__ Al,
    const __half* __restrict__ B,
    const float* __restrict__ bias, float* __restrict__ C,
    __nv_bfloat16* __restrict__ Ch, __nv_bfloat16* __restrict__ Cl, int N)
{
    extern __shared__ char smem[];
    const uint32_t sbase = smem_u32(smem);
    const int tid = threadIdx.x;
    const int wid = tid >> 5, lane = tid & 31;
    const int m0 = blockIdx.y * 128, n0 = blockIdx.x * 128;
    const int wm = wid >> 2, wn = wid & 3;

    const __half* aHb = Ah + (size_t)m0 * KDIM;
    const __half* aLb = Al + (size_t)m0 * KDIM;
    const __half* bBb = B + (size_t)n0 * KDIM;

    float acc[4][4][4];
#pragma unroll
    for (int i = 0; i < 4; i++)
#pragma unroll
        for (int j = 0; j < 4; j++)
#pragma unroll
            for (int v = 0; v < 4; v++) acc[i][j][v] = 0.f;

    const int NC = KDIM / 32;

    auto issue = [&](int stage, int c) {
        const int k0 = c * 32;
        const uint32_t sb = sbase + stage * STAGE_B;
#pragma unroll
        for (int i = 0; i < 2; i++) {
            const int cid = tid + 256 * i;
            const int r = cid >> 2, q = cid & 3;
            const uint32_t so = (r * TS + q * 8) * 2;
            cp16(sb + so, aHb + (size_t)r * KDIM + k0 + q * 8);
            cp16(sb + TILE_B + so, aLb + (size_t)r * KDIM + k0 + q * 8);
            cp16(sb + 2 * TILE_B + so, bBb + (size_t)r * KDIM + k0 + q * 8);
        }
        CP_COMMIT();
    };

    issue(0, 0);

    for (int c = 0; c < NC; c++) {
        CP_WAIT0();
        __syncthreads();
        if (c + 1 < NC) issue((c + 1) & 1, c + 1);

        const int st = c & 1;
        const uint32_t sAh = sbase + st * STAGE_B;
        const uint32_t sAl = sAh + TILE_B;
        const uint32_t sB  = sAh + 2 * TILE_B;

        const int rowa = wm * 64 + (lane & 15);
        const int rowb = wn * 32 + (lane & 15);
        const int ko = (lane >> 4) * 8;

#pragma unroll
        for (int kt = 0; kt < 2; kt++) {
            const int k = kt * 16 + ko;
            uint32_t ah[4][4], al[4][4], bb[2][4];
#pragma unroll
            for (int mt = 0; mt < 4; mt++) {
                ldsm_x4(ah[mt], sAh + ((rowa + mt * 16) * TS + k) * 2);
                ldsm_x4(al[mt], sAl + ((rowa + mt * 16) * TS + k) * 2);
            }
#pragma unroll
            for (int nt = 0; nt < 2; nt++)
                ldsm_x4(bb[nt], sB + ((rowb + nt * 16) * TS + k) * 2);
            // term-major: all Ah*B, then all Al*B
#pragma unroll
            for (int mt = 0; mt < 4; mt++)
#pragma unroll
                for (int nt = 0; nt < 2; nt++)
#pragma unroll
                    for (int h = 0; h < 2; h++)
                        mma_fp16(acc[mt][nt * 2 + h], ah[mt],
                                 bb[nt][h], bb[nt][h + 2]);
#pragma unroll
            for (int mt = 0; mt < 4; mt++)
#pragma unroll
                for (int nt = 0; nt < 2; nt++)
#pragma unroll
                    for (int h = 0; h < 2; h++)
                        mma_fp16(acc[mt][nt * 2 + h], al[mt],
                                 bb[nt][h], bb[nt][h + 2]);
        }
    }

    // epilogue
    const int g = lane >> 2, tig = lane & 3;
#pragma unroll
    for (int mt = 0; mt < 4; mt++) {
#pragma unroll
        for (int n8 = 0; n8 < 4; n8++) {
            const int col = n0 + wn * 32 + n8 * 8 + tig * 2;
            const float2 bv = *reinterpret_cast<const float2*>(bias + col);
            const int row = m0 + wm * 64 + mt * 16 + g;
            float* d = acc[mt][n8];
            float2 o0 = make_float2(d[0] + bv.x, d[1] + bv.y);
            float2 o1 = make_float2(d[2] + bv.x, d[3] + bv.y);
            if constexpr (SPLIT_OUT) {
                __nv_bfloat16 h0, h1, l0, l1;
                split1(o0.x, h0, l0); split1(o0.y, h1, l1);
                *reinterpret_cast<__nv_bfloat162*>(Ch + (size_t)row * N + col) =
                    __nv_bfloat162(h0, h1);
                *reinterpret_cast<__nv_bfloat162*>(Cl + (size_t)row * N + col) =
                    __nv_bfloat162(l0, l1);
                split1(o1.x, h0, l0); split1(o1.y, h1, l1);
                *reinterpret_cast<__nv_bfloat162*>(Ch + (size_t)(row + 8) * N + col) =
                    __nv_bfloat162(h0, h1);
                *reinterpret_cast<__nv_bfloat162*>(Cl + (size_t)(row + 8) * N + col) =
                    __nv_bfloat162(l0, l1);
            } else {
                *reinterpret_cast<float2*>(C + (size_t)row * N + col) = o0;
                *reinterpret_cast<float2*>(C + (size_t)(row + 8) * N + col) = o1;
            }
        }
    }
}

// ---------------- mma.sync flash attention (causal), bf16 3-term ----------
// (validated R9 version; epilogue writes fp16 hi/lo for proj GEMM)
#define AS 72
#define ATILE_B (64 * AS * 2)
#define A_STAGE0 (2 * ATILE_B)
#define A_STAGE_B (4 * ATILE_B)
#define ATTN_SMEM (A_STAGE0 + 2 * A_STAGE_B)  // 92160 B

__global__ __launch_bounds__(128) void attn_mma_kernel(
    const __nv_bfloat16* __restrict__ qkvh,
    const __nv_bfloat16* __restrict__ qkvl,
    __half* __restrict__ yh, __half* __restrict__ yl)
{
    extern __shared__ char smem[];
    const uint32_t sb = smem_u32(smem);
    const int tid = threadIdx.x;
    const int wid = tid >> 5, lane = tid & 31;
    const int g = lane >> 2, tig = lane & 3;

    const int bh = blockIdx.y;
    const int b = bh >> 4, h = bh & 15;
    const int qt = (int)gridDim.x - 1 - (int)blockIdx.x;
    const int q0 = qt * 64;

    const size_t rowbase = (size_t)b * SEQ * QKV_N + h * HD;
    const uint32_t sQh = sb, sQl = sb + ATILE_B;

    auto issueKV = [&](int stage, int kt) {
        const int k0 = kt * 64;
        const uint32_t sbK = sb + A_STAGE0 + stage * A_STAGE_B;
#pragma unroll
        for (int i = 0; i < 4; i++) {
            const int cid = tid + 128 * i;
            const int r = cid >> 3, q = cid & 7;
            const size_t gK = rowbase + (size_t)(k0 + r) * QKV_N + D_MODEL + q * 8;
            const size_t gV = gK + D_MODEL;
            const uint32_t so = (r * AS + q * 8) * 2;
            cp16(sbK + so, qkvh + gK);
            cp16(sbK + ATILE_B + so, qkvl + gK);
            cp16(sbK + 2 * ATILE_B + so, qkvh + gV);
            cp16(sbK + 3 * ATILE_B + so, qkvl + gV);
        }
        CP_COMMIT();
    };

    {
#pragma unroll
        for (int i = 0; i < 4; i++) {
            const int cid = tid + 128 * i;
            const int r = cid >> 3, q = cid & 7;
            const size_t go = rowbase + (size_t)(q0 + r) * QKV_N + q * 8;
            cp16(sQh + (r * AS + q * 8) * 2, qkvh + go);
            cp16(sQl + (r * AS + q * 8) * 2, qkvl + go);
        }
    }
    issueKV(0, 0);

    float m[2], l[2], oacc[8][4];
    m[0] = m[1] = -INFINITY;
    l[0] = l[1] = 0.f;
#pragma unroll
    for (int t = 0; t < 8; t++)
#pragma unroll
        for (int v = 0; v < 4; v++) oacc[t][v] = 0.f;

    uint32_t qh[4][4], ql[4][4];
    bool qloaded = false;
    const float scale = 0.125f;
    const int rowa = wid * 16 + (lane & 15);
    const int ko = (lane >> 4) * 8;

    for (int kt = 0; kt <= qt; kt++) {
        CP_WAIT0();
        __syncthreads();
        if (kt < qt) issueKV((kt + 1) & 1, kt + 1);

        const uint32_t sK = sb + A_STAGE0 + (kt & 1) * A_STAGE_B;
        const uint32_t sKh = sK, sKl = sK + ATILE_B;
        const uint32_t sVh = sK + 2 * ATILE_B, sVl = sK + 3 * ATILE_B;

        if (!qloaded) {
#pragma unroll
            for (int kc = 0; kc < 4; kc++) {
                ldsm_x4(qh[kc], sQh + (rowa * AS + kc * 16 + ko) * 2);
                ldsm_x4(ql[kc], sQl + (rowa * AS + kc * 16 + ko) * 2);
            }
            qloaded = true;
        }

        float sacc[8][4];
#pragma unroll
        for (int t = 0; t < 8; t++)
#pragma unroll
            for (int v = 0; v < 4; v++) sacc[t][v] = 0.f;

#pragma unroll
        for (int kc = 0; kc < 4; kc++) {
            uint32_t kbh[4][4], kbl[4][4];
#pragma unroll
            for (int nt = 0; nt < 4; nt++) {
                const uint32_t ka = ((nt * 16 + (lane & 15)) * AS + kc * 16 + ko) * 2;
                ldsm_x4(kbh[nt], sKh + ka);
                ldsm_x4(kbl[nt], sKl + ka);
            }
#pragma unroll
            for (int nt = 0; nt < 4; nt++)
#pragma unroll
                for (int hh = 0; hh < 2; hh++)
                    mma_bf16(sacc[nt * 2 + hh], qh[kc],
                             kbh[nt][hh], kbh[nt][hh + 2]);
#pragma unroll
            for (int nt = 0; nt < 4; nt++)
#pragma unroll
                for (int hh = 0; hh < 2; hh++)
                    mma_bf16(sacc[nt * 2 + hh], qh[kc],
                             kbl[nt][hh], kbl[nt][hh + 2]);
#pragma unroll
            for (int nt = 0; nt < 4; nt++)
#pragma unroll
                for (int hh = 0; hh < 2; hh++)
                    mma_bf16(sacc[nt * 2 + hh], ql[kc],
                             kbh[nt][hh], kbh[nt][hh + 2]);
        }

        const int k0 = kt * 64;
        if (kt == qt) {
#pragma unroll
            for (int t = 0; t < 8; t++)
#pragma unroll
                for (int v = 0; v < 4; v++) {
                    const int kg = k0 + t * 8 + 2 * tig + (v & 1);
                    const int qg = q0 + wid * 16 + g + (v >> 1) * 8;
                    sacc[t][v] = (kg <= qg) ? sacc[t][v] * scale : -INFINITY;
                }
        } else {
#pragma unroll
            for (int t = 0; t < 8; t++)
#pragma unroll
                for (int v = 0; v < 4; v++) sacc[t][v] *= scale;
        }

#pragma unroll
        for (int rh = 0; rh < 2; rh++) {
            float mt = -INFINITY;
#pragma unroll
            for (int t = 0; t < 8; t++)
                mt = fmaxf(mt, fmaxf(sacc[t][rh * 2], sacc[t][rh * 2 + 1]));
            mt = fmaxf(mt, __shfl_xor_sync(0xffffffffu, mt, 1));
            mt = fmaxf(mt, __shfl_xor_sync(0xffffffffu, mt, 2));
            const float mn = fmaxf(m[rh], mt);
            const float corr = __expf(m[rh] - mn);
            m[rh] = mn;
            float ps = 0.f;
#pragma unroll
            for (int t = 0; t < 8; t++) {
                float p0 = __expf(sacc[t][rh * 2] - mn);
                float p1 = __expf(sacc[t][rh * 2 + 1] - mn);
                sacc[t][rh * 2] = p0;
                sacc[t][rh * 2 + 1] = p1;
                ps += p0 + p1;
            }
            ps += __shfl_xor_sync(0xffffffffu, ps, 1);
            ps += __shfl_xor_sync(0xffffffffu, ps, 2);
            l[rh] = l[rh] * corr + ps;
#pragma unroll
            for (int t = 0; t < 8; t++) {
                oacc[t][rh * 2] *= corr;
                oacc[t][rh * 2 + 1] *= corr;
            }
        }

        uint32_t ph[8][2], pl[8][2];
#pragma unroll
        for (int t = 0; t < 8; t++)
#pragma unroll
            for (int rh = 0; rh < 2; rh++) {
                float2 f = make_float2(sacc[t][rh * 2], sacc[t][rh * 2 + 1]);
                __nv_bfloat162 h2 = __floats2bfloat162_rn(f.x, f.y);
                float2 bk = __bfloat1622float2(h2);
                __nv_bfloat162 l2 = __floats2bfloat162_rn(f.x - bk.x, f.y - bk.y);
                ph[t][rh] = *reinterpret_cast<uint32_t*>(&h2);
                pl[t][rh] = *reinterpret_cast<uint32_t*>(&l2);
            }

        const int vrow = ((lane >> 4) & 1) * 8 + (lane & 7);
        const int vcol = ((lane >> 3) & 1) * 8;
#pragma unroll
        for (int jc = 0; jc < 4; jc++) {
            uint32_t pa_h[4] = {ph[2 * jc][0], ph[2 * jc][1],
                                ph[2 * jc + 1][0], ph[2 * jc + 1][1]};
            uint32_t pa_l[4] = {pl[2 * jc][0], pl[2 * jc][1],
                                pl[2 * jc + 1][0], pl[2 * jc + 1][1]};
            uint32_t vbh[4][4], vbl[4][4];
#pragma unroll
            for (int dt = 0; dt < 4; dt++) {
                const uint32_t va = ((jc * 16 + vrow) * AS + dt * 16 + vcol) * 2;
                ldsm_x4_t(vbh[dt], sVh + va);
                ldsm_x4_t(vbl[dt], sVl + va);
            }
#pragma unroll
            for (int dt = 0; dt < 4; dt++)
#pragma unroll
                for (int hh = 0; hh < 2; hh++)
                    mma_bf16(oacc[dt * 2 + hh], pa_h,
                             vbh[dt][hh], vbh[dt][hh + 2]);
#pragma unroll
            for (int dt = 0; dt < 4; dt++)
#pragma unroll
                for (int hh = 0; hh < 2; hh++)
                    mma_bf16(oacc[dt * 2 + hh], pa_h,
                             vbl[dt][hh], vbl[dt][hh + 2]);
#pragma unroll
            for (int dt = 0; dt < 4; dt++)
#pragma unroll
                for (int hh = 0; hh < 2; hh++)
                    mma_bf16(oacc[dt * 2 + hh], pa_l,
                             vbh[dt][hh], vbh[dt][hh + 2]);
        }
    }

    // epilogue: write y split fp16 hi/lo (feeds proj GEMM A-operand)
    const float inv0 = 1.f / l[0], inv1 = 1.f / l[1];
    const int row0 = q0 + wid * 16 + g;
#pragma unroll
    for (int t = 0; t < 8; t++) {
        const int col = h * HD + t * 8 + 2 * tig;
        const size_t o0i = ((size_t)b * SEQ + row0) * D_MODEL + col;
        const size_t o1i = ((size_t)b * SEQ + row0 + 8) * D_MODEL + col;
        __half h0, h1, l0, l1;
        split1h(oacc[t][0] * inv0, h0, l0);
        split1h(oacc[t][1] * inv0, h1, l1);
        *reinterpret_cast<__half2*>(yh + o0i) = __half2(h0, h1);
        *reinterpret_cast<__half2*>(yl + o0i) = __half2(l0, l1);
        split1h(oacc[t][2] * inv1, h0, l0);
        split1h(oacc[t][3] * inv1, h1, l1);
        *reinterpret_cast<__half2*>(yh + o1i) = __half2(h0, h1);
        *reinterpret_cast<__half2*>(yl + o1i) = __half2(l0, l1);
    }
}

// ---------------------------------------------------------------------------
extern "C" void kernel_launch(void* const* d_in, const int* in_sizes, int n_in,
                              void* d_out, int out_size)
{
    const float* x      = (const float*)d_in[0];
    const float* W_attn = (const float*)d_in[1];
    const float* b_attn = (const float*)d_in[2];
    const float* W_proj = (const float*)d_in[3];
    const float* b_proj = (const float*)d_in[4];
    float* out = (float*)d_out;

    __half *xh, *xl, *yh, *yl, *wat, *wpt;
    __nv_bfloat16 *qvh, *qvl;
    cudaGetSymbolAddress((void**)&xh, g_x_hi);
    cudaGetSymbolAddress((void**)&xl, g_x_lo);
    cudaGetSymbolAddress((void**)&yh, g_y_hi);
    cudaGetSymbolAddress((void**)&yl, g_y_lo);
    cudaGetSymbolAddress((void**)&qvh, g_qkv_hi);
    cudaGetSymbolAddress((void**)&qvl, g_qkv_lo);
    cudaGetSymbolAddress((void**)&wat, g_wat);
    cudaGetSymbolAddress((void**)&wpt, g_wpt);

    cudaFuncSetAttribute(gemm_mma_kernel<true>,
                         cudaFuncAttributeMaxDynamicSharedMemorySize, GEMM_SMEM);
    cudaFuncSetAttribute(gemm_mma_kernel<false>,
                         cudaFuncAttributeMaxDynamicSharedMemorySize, GEMM_SMEM);
    cudaFuncSetAttribute(attn_mma_kernel,
                         cudaFuncAttributeMaxDynamicSharedMemorySize, ATTN_SMEM);

    const int NX = M_TOTAL * KDIM;

    // prep: x -> fp16 hi/lo; weights -> fp16 transposed
    split_half_kernel<<<NX / (256 * 4), 256>>>(x, xh, xl, NX);
    transpose_half_kernel<<<dim3(QKV_N / 32, KDIM / 32), dim3(32, 8)>>>(
        W_attn, wat, KDIM, QKV_N);
    transpose_half_kernel<<<dim3(D_MODEL / 32, KDIM / 32), dim3(32, 8)>>>(
        W_proj, wpt, KDIM, D_MODEL);

    // 1) qkv = x @ W_attn + b_attn  -> bf16 hi/lo for attention
    gemm_mma_kernel<true><<<dim3(QKV_N / 128, M_TOTAL / 128), 256, GEMM_SMEM>>>(
        xh, xl, wat, b_attn, nullptr, qvh, qvl, QKV_N);

    // 2) flash attention (bf16 3-term) -> y fp16 hi/lo
    attn_mma_kernel<<<dim3(SEQ / 64, BATCH * N_HEADS), 128, ATTN_SMEM>>>(
        qvh, qvl, yh, yl);

    // 3) out = y @ W_proj + b_proj (fp32 out)
    gemm_mma_kernel<false><<<dim3(D_MODEL / 128, M_TOTAL / 128), 256, GEMM_SMEM>>>(
        yh, yl, wpt, b_proj, out, nullptr, nullptr, D_MODEL);
}

// round 12
// speedup vs baseline: 2.3290x; 1.0882x over previous
#include <cuda_runtime.h>
#include <cuda_bf16.h>
#include <cuda_fp16.h>
#include <math.h>
#include <stdint.h>

#define D_MODEL 1024
#define N_HEADS 16
#define HD 64
#define BATCH 2
#define SEQ 2048
#define M_TOTAL (BATCH * SEQ)   // 4096
#define QKV_N (3 * D_MODEL)     // 3072
#define KDIM 1024

// ---------------- scratch (device globals; allocation-free) ----------------
__device__ __align__(256) __half g_x_hi[(size_t)M_TOTAL * KDIM];
__device__ __align__(256) __half g_x_lo[(size_t)M_TOTAL * KDIM];
__device__ __align__(256) __half g_y_hi[(size_t)M_TOTAL * KDIM];
__device__ __align__(256) __half g_y_lo[(size_t)M_TOTAL * KDIM];
__device__ __align__(256) __half g_qkv_hi[(size_t)M_TOTAL * QKV_N];
__device__ __align__(256) __half g_qkv_lo[(size_t)M_TOTAL * QKV_N];
__device__ __align__(256) __half g_wat[(size_t)QKV_N * KDIM];   // W_attn^T fp16
__device__ __align__(256) __half g_wpt[(size_t)D_MODEL * KDIM]; // W_proj^T fp16

// ---------------- helpers ----------------
__device__ __forceinline__ uint32_t smem_u32(const void* p) {
    uint32_t a;
    asm("{ .reg .u64 t; cvta.to.shared.u64 t, %1; cvt.u32.u64 %0, t; }"
        : "=r"(a) : "l"(p));
    return a;
}

__device__ __forceinline__ void cp16(uint32_t dst, const void* src) {
    asm volatile("cp.async.cg.shared.global [%0], [%1], 16;" :: "r"(dst), "l"(src));
}
#define CP_COMMIT() asm volatile("cp.async.commit_group;" ::: "memory")
#define CP_WAIT0()  asm volatile("cp.async.wait_group 0;" ::: "memory")

__device__ __forceinline__ void ldsm_x4(uint32_t* r, uint32_t addr) {
    asm volatile("ldmatrix.sync.aligned.m8n8.x4.shared.b16 {%0,%1,%2,%3}, [%4];"
        : "=r"(r[0]), "=r"(r[1]), "=r"(r[2]), "=r"(r[3]) : "r"(addr));
}
__device__ __forceinline__ void ldsm_x4_t(uint32_t* r, uint32_t addr) {
    asm volatile("ldmatrix.sync.aligned.m8n8.x4.trans.shared.b16 {%0,%1,%2,%3}, [%4];"
        : "=r"(r[0]), "=r"(r[1]), "=r"(r[2]), "=r"(r[3]) : "r"(addr));
}

__device__ __forceinline__ void mma_fp16(float* d, const uint32_t* a,
                                         uint32_t b0, uint32_t b1) {
    asm volatile(
        "mma.sync.aligned.m16n8k16.row.col.f32.f16.f16.f32 "
        "{%0,%1,%2,%3}, {%4,%5,%6,%7}, {%8,%9}, {%0,%1,%2,%3};"
        : "+f"(d[0]), "+f"(d[1]), "+f"(d[2]), "+f"(d[3])
        : "r"(a[0]), "r"(a[1]), "r"(a[2]), "r"(a[3]), "r"(b0), "r"(b1));
}

// ---------------- conversion kernels ----------------
__device__ __forceinline__ void split1h(float v, __half& h, __half& l) {
    h = __float2half_rn(v);
    l = __float2half_rn(v - __half2float(h));
}

// float -> fp16 hi/lo
__global__ void split_half_kernel(const float* __restrict__ in,
                                  __half* __restrict__ hi,
                                  __half* __restrict__ lo, int n)
{
    int idx = (blockIdx.x * blockDim.x + threadIdx.x) * 4;
    if (idx >= n) return;
    float4 v = *reinterpret_cast<const float4*>(in + idx);
    __half h0, h1, h2, h3, l0, l1, l2, l3;
    split1h(v.x, h0, l0); split1h(v.y, h1, l1);
    split1h(v.z, h2, l2); split1h(v.w, h3, l3);
    *reinterpret_cast<__half2*>(hi + idx)     = __half2(h0, h1);
    *reinterpret_cast<__half2*>(hi + idx + 2) = __half2(h2, h3);
    *reinterpret_cast<__half2*>(lo + idx)     = __half2(l0, l1);
    *reinterpret_cast<__half2*>(lo + idx + 2) = __half2(l2, l3);
}

// W [K,N] -> Wt [N,K] fp16 single
__global__ void transpose_half_kernel(const float* __restrict__ W,
                                      __half* __restrict__ t16, int K, int N)
{
    __shared__ float t[32][33];
    const int tx = threadIdx.x, ty = threadIdx.y;
    const int n0 = blockIdx.x * 32, k0 = blockIdx.y * 32;
#pragma unroll
    for (int j = ty; j < 32; j += 8)
        t[j][tx] = W[(size_t)(k0 + j) * N + n0 + tx];
    __syncthreads();
#pragma unroll
    for (int j = ty; j < 32; j += 8)
        t16[(size_t)(n0 + j) * K + k0 + tx] = __float2half_rn(t[tx][j]);
}

// ---------------- mma.sync fp16 2-term GEMM (validated R11) ----------------
// C[M,N] = (Ah + Al)[M,K] @ B[N,K]^T + bias, fp32 acc.
// SPLIT_OUT: write fp16 hi/lo (feeds attention).
#define TS 40
#define TILE_B (128 * TS * 2)          // 10240 B
#define STAGE_B (3 * TILE_B)           // Ah, Al, B
#define GEMM_SMEM (2 * STAGE_B)        // 61440 B

template <bool SPLIT_OUT>
__global__ __launch_bounds__(256) void gemm_mma_kernel(
    const __half* __restrict__ Ah, const __half* __restrict__ Al,
    const __half* __restrict__ B,
    const float* __restrict__ bias, float* __restrict__ C,
    __half* __restrict__ Ch, __half* __restrict__ Cl, int N)
{
    extern __shared__ char smem[];
    const uint32_t sbase = smem_u32(smem);
    const int tid = threadIdx.x;
    const int wid = tid >> 5, lane = tid & 31;
    const int m0 = blockIdx.y * 128, n0 = blockIdx.x * 128;
    const int wm = wid >> 2, wn = wid & 3;

    const __half* aHb = Ah + (size_t)m0 * KDIM;
    const __half* aLb = Al + (size_t)m0 * KDIM;
    const __half* bBb = B + (size_t)n0 * KDIM;

    float acc[4][4][4];
#pragma unroll
    for (int i = 0; i < 4; i++)
#pragma unroll
        for (int j = 0; j < 4; j++)
#pragma unroll
            for (int v = 0; v < 4; v++) acc[i][j][v] = 0.f;

    const int NC = KDIM / 32;

    auto issue = [&](int stage, int c) {
        const int k0 = c * 32;
        const uint32_t sb = sbase + stage * STAGE_B;
#pragma unroll
        for (int i = 0; i < 2; i++) {
            const int cid = tid + 256 * i;
            const int r = cid >> 2, q = cid & 3;
            const uint32_t so = (r * TS + q * 8) * 2;
            cp16(sb + so, aHb + (size_t)r * KDIM + k0 + q * 8);
            cp16(sb + TILE_B + so, aLb + (size_t)r * KDIM + k0 + q * 8);
            cp16(sb + 2 * TILE_B + so, bBb + (size_t)r * KDIM + k0 + q * 8);
        }
        CP_COMMIT();
    };

    issue(0, 0);

    for (int c = 0; c < NC; c++) {
        CP_WAIT0();
        __syncthreads();
        if (c + 1 < NC) issue((c + 1) & 1, c + 1);

        const int st = c & 1;
        const uint32_t sAh = sbase + st * STAGE_B;
        const uint32_t sAl = sAh + TILE_B;
        const uint32_t sB  = sAh + 2 * TILE_B;

        const int rowa = wm * 64 + (lane & 15);
        const int rowb = wn * 32 + (lane & 15);
        const int ko = (lane >> 4) * 8;

#pragma unroll
        for (int kt = 0; kt < 2; kt++) {
            const int k = kt * 16 + ko;
            uint32_t ah[4][4], al[4][4], bb[2][4];
#pragma unroll
            for (int mt = 0; mt < 4; mt++) {
                ldsm_x4(ah[mt], sAh + ((rowa + mt * 16) * TS + k) * 2);
                ldsm_x4(al[mt], sAl + ((rowa + mt * 16) * TS + k) * 2);
            }
#pragma unroll
            for (int nt = 0; nt < 2; nt++)
                ldsm_x4(bb[nt], sB + ((rowb + nt * 16) * TS + k) * 2);
            // term-major: all Ah*B, then all Al*B
#pragma unroll
            for (int mt = 0; mt < 4; mt++)
#pragma unroll
                for (int nt = 0; nt < 2; nt++)
#pragma unroll
                    for (int h = 0; h < 2; h++)
                        mma_fp16(acc[mt][nt * 2 + h], ah[mt],
                                 bb[nt][h], bb[nt][h + 2]);
#pragma unroll
            for (int mt = 0; mt < 4; mt++)
#pragma unroll
                for (int nt = 0; nt < 2; nt++)
#pragma unroll
                    for (int h = 0; h < 2; h++)
                        mma_fp16(acc[mt][nt * 2 + h], al[mt],
                                 bb[nt][h], bb[nt][h + 2]);
        }
    }

    // epilogue
    const int g = lane >> 2, tig = lane & 3;
#pragma unroll
    for (int mt = 0; mt < 4; mt++) {
#pragma unroll
        for (int n8 = 0; n8 < 4; n8++) {
            const int col = n0 + wn * 32 + n8 * 8 + tig * 2;
            const float2 bv = *reinterpret_cast<const float2*>(bias + col);
            const int row = m0 + wm * 64 + mt * 16 + g;
            float* d = acc[mt][n8];
            float2 o0 = make_float2(d[0] + bv.x, d[1] + bv.y);
            float2 o1 = make_float2(d[2] + bv.x, d[3] + bv.y);
            if constexpr (SPLIT_OUT) {
                __half h0, h1, l0, l1;
                split1h(o0.x, h0, l0); split1h(o0.y, h1, l1);
                *reinterpret_cast<__half2*>(Ch + (size_t)row * N + col) = __half2(h0, h1);
                *reinterpret_cast<__half2*>(Cl + (size_t)row * N + col) = __half2(l0, l1);
                split1h(o1.x, h0, l0); split1h(o1.y, h1, l1);
                *reinterpret_cast<__half2*>(Ch + (size_t)(row + 8) * N + col) = __half2(h0, h1);
                *reinterpret_cast<__half2*>(Cl + (size_t)(row + 8) * N + col) = __half2(l0, l1);
            } else {
                *reinterpret_cast<float2*>(C + (size_t)row * N + col) = o0;
                *reinterpret_cast<float2*>(C + (size_t)(row + 8) * N + col) = o1;
            }
        }
    }
}

// ---------------- mma.sync flash attention (causal), fp16 ----------------
// S = QhKh + QhKl + QlKh (3-term, 22-bit Q/K); PV = (Ph+Pl)*Vh (2-term,
// V single fp16 — error averages out under softmax weights).
// K hi/lo + V hi = 3 cp.async streams; smem 74KB -> 3 CTAs/SM.
#define AS 72
#define ATILE_B (64 * AS * 2)          // 9216 B
#define A_STAGE0 (2 * ATILE_B)         // Qh, Ql
#define A_STAGE_B (3 * ATILE_B)        // Kh, Kl, Vh
#define ATTN_SMEM (A_STAGE0 + 2 * A_STAGE_B)  // 73728 B

__global__ __launch_bounds__(128) void attn_mma_kernel(
    const __half* __restrict__ qkvh,
    const __half* __restrict__ qkvl,
    __half* __restrict__ yh, __half* __restrict__ yl)
{
    extern __shared__ char smem[];
    const uint32_t sb = smem_u32(smem);
    const int tid = threadIdx.x;
    const int wid = tid >> 5, lane = tid & 31;
    const int g = lane >> 2, tig = lane & 3;

    const int bh = blockIdx.y;
    const int b = bh >> 4, h = bh & 15;
    const int qt = (int)gridDim.x - 1 - (int)blockIdx.x;  // longest first
    const int q0 = qt * 64;

    const size_t rowbase = (size_t)b * SEQ * QKV_N + h * HD;
    const uint32_t sQh = sb, sQl = sb + ATILE_B;

    auto issueKV = [&](int stage, int kt) {
        const int k0 = kt * 64;
        const uint32_t sbK = sb + A_STAGE0 + stage * A_STAGE_B;
#pragma unroll
        for (int i = 0; i < 4; i++) {
            const int cid = tid + 128 * i;
            const int r = cid >> 3, q = cid & 7;
            const size_t gK = rowbase + (size_t)(k0 + r) * QKV_N + D_MODEL + q * 8;
            const size_t gV = gK + D_MODEL;
            const uint32_t so = (r * AS + q * 8) * 2;
            cp16(sbK + so, qkvh + gK);
            cp16(sbK + ATILE_B + so, qkvl + gK);
            cp16(sbK + 2 * ATILE_B + so, qkvh + gV);
        }
        CP_COMMIT();
    };

    {
#pragma unroll
        for (int i = 0; i < 4; i++) {
            const int cid = tid + 128 * i;
            const int r = cid >> 3, q = cid & 7;
            const size_t go = rowbase + (size_t)(q0 + r) * QKV_N + q * 8;
            cp16(sQh + (r * AS + q * 8) * 2, qkvh + go);
            cp16(sQl + (r * AS + q * 8) * 2, qkvl + go);
        }
    }
    issueKV(0, 0);

    float m[2], l[2], oacc[8][4];
    m[0] = m[1] = -INFINITY;
    l[0] = l[1] = 0.f;
#pragma unroll
    for (int t = 0; t < 8; t++)
#pragma unroll
        for (int v = 0; v < 4; v++) oacc[t][v] = 0.f;

    uint32_t qh[4][4], ql[4][4];
    bool qloaded = false;
    const float scale = 0.125f;
    const int rowa = wid * 16 + (lane & 15);
    const int ko = (lane >> 4) * 8;

    for (int kt = 0; kt <= qt; kt++) {
        CP_WAIT0();
        __syncthreads();
        if (kt < qt) issueKV((kt + 1) & 1, kt + 1);

        const uint32_t sK = sb + A_STAGE0 + (kt & 1) * A_STAGE_B;
        const uint32_t sKh = sK, sKl = sK + ATILE_B;
        const uint32_t sVh = sK + 2 * ATILE_B;

        if (!qloaded) {
#pragma unroll
            for (int kc = 0; kc < 4; kc++) {
                ldsm_x4(qh[kc], sQh + (rowa * AS + kc * 16 + ko) * 2);
                ldsm_x4(ql[kc], sQl + (rowa * AS + kc * 16 + ko) * 2);
            }
            qloaded = true;
        }

        // ---- S = Q K^T (3-term fp16, term-major per kc slice) ----
        float sacc[8][4];
#pragma unroll
        for (int t = 0; t < 8; t++)
#pragma unroll
            for (int v = 0; v < 4; v++) sacc[t][v] = 0.f;

#pragma unroll
        for (int kc = 0; kc < 4; kc++) {
            uint32_t kbh[4][4], kbl[4][4];
#pragma unroll
            for (int nt = 0; nt < 4; nt++) {
                const uint32_t ka = ((nt * 16 + (lane & 15)) * AS + kc * 16 + ko) * 2;
                ldsm_x4(kbh[nt], sKh + ka);
                ldsm_x4(kbl[nt], sKl + ka);
            }
#pragma unroll
            for (int nt = 0; nt < 4; nt++)
#pragma unroll
                for (int hh = 0; hh < 2; hh++)
                    mma_fp16(sacc[nt * 2 + hh], qh[kc],
                             kbh[nt][hh], kbh[nt][hh + 2]);
#pragma unroll
            for (int nt = 0; nt < 4; nt++)
#pragma unroll
                for (int hh = 0; hh < 2; hh++)
                    mma_fp16(sacc[nt * 2 + hh], qh[kc],
                             kbl[nt][hh], kbl[nt][hh + 2]);
#pragma unroll
            for (int nt = 0; nt < 4; nt++)
#pragma unroll
                for (int hh = 0; hh < 2; hh++)
                    mma_fp16(sacc[nt * 2 + hh], ql[kc],
                             kbh[nt][hh], kbh[nt][hh + 2]);
        }

        // scale + causal mask
        const int k0 = kt * 64;
        if (kt == qt) {
#pragma unroll
            for (int t = 0; t < 8; t++)
#pragma unroll
                for (int v = 0; v < 4; v++) {
                    const int kg = k0 + t * 8 + 2 * tig + (v & 1);
                    const int qg = q0 + wid * 16 + g + (v >> 1) * 8;
                    sacc[t][v] = (kg <= qg) ? sacc[t][v] * scale : -INFINITY;
                }
        } else {
#pragma unroll
            for (int t = 0; t < 8; t++)
#pragma unroll
                for (int v = 0; v < 4; v++) sacc[t][v] *= scale;
        }

        // online softmax
#pragma unroll
        for (int rh = 0; rh < 2; rh++) {
            float mt = -INFINITY;
#pragma unroll
            for (int t = 0; t < 8; t++)
                mt = fmaxf(mt, fmaxf(sacc[t][rh * 2], sacc[t][rh * 2 + 1]));
            mt = fmaxf(mt, __shfl_xor_sync(0xffffffffu, mt, 1));
            mt = fmaxf(mt, __shfl_xor_sync(0xffffffffu, mt, 2));
            const float mn = fmaxf(m[rh], mt);
            const float corr = __expf(m[rh] - mn);
            m[rh] = mn;
            float ps = 0.f;
#pragma unroll
            for (int t = 0; t < 8; t++) {
                float p0 = __expf(sacc[t][rh * 2] - mn);
                float p1 = __expf(sacc[t][rh * 2 + 1] - mn);
                sacc[t][rh * 2] = p0;
                sacc[t][rh * 2 + 1] = p1;
                ps += p0 + p1;
            }
            ps += __shfl_xor_sync(0xffffffffu, ps, 1);
            ps += __shfl_xor_sync(0xffffffffu, ps, 2);
            l[rh] = l[rh] * corr + ps;
#pragma unroll
            for (int t = 0; t < 8; t++) {
                oacc[t][rh * 2] *= corr;
                oacc[t][rh * 2 + 1] *= corr;
            }
        }

        // P -> fp16 hi/lo fragments (22-bit exact)
        uint32_t ph[8][2], pl[8][2];
#pragma unroll
        for (int t = 0; t < 8; t++)
#pragma unroll
            for (int rh = 0; rh < 2; rh++) {
                float2 f = make_float2(sacc[t][rh * 2], sacc[t][rh * 2 + 1]);
                __half2 h2 = __floats2half2_rn(f.x, f.y);
                float2 bk = __half22float2(h2);
                __half2 l2 = __floats2half2_rn(f.x - bk.x, f.y - bk.y);
                ph[t][rh] = *reinterpret_cast<uint32_t*>(&h2);
                pl[t][rh] = *reinterpret_cast<uint32_t*>(&l2);
            }

        // ---- O += P V (2-term, V single fp16, term-major per jc slice) ----
        const int vrow = ((lane >> 4) & 1) * 8 + (lane & 7);
        const int vcol = ((lane >> 3) & 1) * 8;
#pragma unroll
        for (int jc = 0; jc < 4; jc++) {
            uint32_t pa_h[4] = {ph[2 * jc][0], ph[2 * jc][1],
                                ph[2 * jc + 1][0], ph[2 * jc + 1][1]};
            uint32_t pa_l[4] = {pl[2 * jc][0], pl[2 * jc][1],
                                pl[2 * jc + 1][0], pl[2 * jc + 1][1]};
            uint32_t vbh[4][4];
#pragma unroll
            for (int dt = 0; dt < 4; dt++) {
                const uint32_t va = ((jc * 16 + vrow) * AS + dt * 16 + vcol) * 2;
                ldsm_x4_t(vbh[dt], sVh + va);
            }
#pragma unroll
            for (int dt = 0; dt < 4; dt++)
#pragma unroll
                for (int hh = 0; hh < 2; hh++)
                    mma_fp16(oacc[dt * 2 + hh], pa_h,
                             vbh[dt][hh], vbh[dt][hh + 2]);
#pragma unroll
            for (int dt = 0; dt < 4; dt++)
#pragma unroll
                for (int hh = 0; hh < 2; hh++)
                    mma_fp16(oacc[dt * 2 + hh], pa_l,
                             vbh[dt][hh], vbh[dt][hh + 2]);
        }
    }

    // epilogue: write y split fp16 hi/lo (feeds proj GEMM A-operand)
    const float inv0 = 1.f / l[0], inv1 = 1.f / l[1];
    const int row0 = q0 + wid * 16 + g;
#pragma unroll
    for (int t = 0; t < 8; t++) {
        const int col = h * HD + t * 8 + 2 * tig;
        const size_t o0i = ((size_t)b * SEQ + row0) * D_MODEL + col;
        const size_t o1i = ((size_t)b * SEQ + row0 + 8) * D_MODEL + col;
        __half h0, h1, l0, l1;
        split1h(oacc[t][0] * inv0, h0, l0);
        split1h(oacc[t][1] * inv0, h1, l1);
        *reinterpret_cast<__half2*>(yh + o0i) = __half2(h0, h1);
        *reinterpret_cast<__half2*>(yl + o0i) = __half2(l0, l1);
        split1h(oacc[t][2] * inv1, h0, l0);
        split1h(oacc[t][3] * inv1, h1, l1);
        *reinterpret_cast<__half2*>(yh + o1i) = __half2(h0, h1);
        *reinterpret_cast<__half2*>(yl + o1i) = __half2(l0, l1);
    }
}

// ---------------------------------------------------------------------------
extern "C" void kernel_launch(void* const* d_in, const int* in_sizes, int n_in,
                              void* d_out, int out_size)
{
    const float* x      = (const float*)d_in[0];
    const float* W_attn = (const float*)d_in[1];
    const float* b_attn = (const float*)d_in[2];
    const float* W_proj = (const float*)d_in[3];
    const float* b_proj = (const float*)d_in[4];
    float* out = (float*)d_out;

    __half *xh, *xl, *yh, *yl, *qvh, *qvl, *wat, *wpt;
    cudaGetSymbolAddress((void**)&xh, g_x_hi);
    cudaGetSymbolAddress((void**)&xl, g_x_lo);
    cudaGetSymbolAddress((void**)&yh, g_y_hi);
    cudaGetSymbolAddress((void**)&yl, g_y_lo);
    cudaGetSymbolAddress((void**)&qvh, g_qkv_hi);
    cudaGetSymbolAddress((void**)&qvl, g_qkv_lo);
    cudaGetSymbolAddress((void**)&wat, g_wat);
    cudaGetSymbolAddress((void**)&wpt, g_wpt);

    cudaFuncSetAttribute(gemm_mma_kernel<true>,
                         cudaFuncAttributeMaxDynamicSharedMemorySize, GEMM_SMEM);
    cudaFuncSetAttribute(gemm_mma_kernel<false>,
                         cudaFuncAttributeMaxDynamicSharedMemorySize, GEMM_SMEM);
    cudaFuncSetAttribute(attn_mma_kernel,
                         cudaFuncAttributeMaxDynamicSharedMemorySize, ATTN_SMEM);

    const int NX = M_TOTAL * KDIM;

    // prep: x -> fp16 hi/lo; weights -> fp16 transposed
    split_half_kernel<<<NX / (256 * 4), 256>>>(x, xh, xl, NX);
    transpose_half_kernel<<<dim3(QKV_N / 32, KDIM / 32), dim3(32, 8)>>>(
        W_attn, wat, KDIM, QKV_N);
    transpose_half_kernel<<<dim3(D_MODEL / 32, KDIM / 32), dim3(32, 8)>>>(
        W_proj, wpt, KDIM, D_MODEL);

    // 1) qkv = x @ W_attn + b_attn  -> fp16 hi/lo for attention
    gemm_mma_kernel<true><<<dim3(QKV_N / 128, M_TOTAL / 128), 256, GEMM_SMEM>>>(
        xh, xl, wat, b_attn, nullptr, qvh, qvl, QKV_N);

    // 2) flash attention (fp16: S 3-term, PV 2-term) -> y fp16 hi/lo
    attn_mma_kernel<<<dim3(SEQ / 64, BATCH * N_HEADS), 128, ATTN_SMEM>>>(
        qvh, qvl, yh, yl);

    // 3) out = y @ W_proj + b_proj (fp32 out)
    gemm_mma_kernel<false><<<dim3(D_MODEL / 128, M_TOTAL / 128), 256, GEMM_SMEM>>>(
        yh, yl, wpt, b_proj, out, nullptr, nullptr, D_MODEL);
}